// round 1
// baseline (speedup 1.0000x reference)
#include <cuda_runtime.h>
#include <cuda_bf16.h>
#include <cstdint>

// Problem constants
#define LQ 2048
#define SK 2048
#define BB 4
#define EE 1024
#define HH 16
#define HD 64
#define FF 4096
#define MM (LQ * BB)   // 8192 rows

// ---------------------------------------------------------------------------
// Scratch buffers (__device__ globals: allocation-free per harness rules)
// ---------------------------------------------------------------------------
__device__ float g_Q[MM * EE];
__device__ float g_K[MM * EE];
__device__ float g_V[MM * EE];
__device__ float g_A[MM * EE];
__device__ float g_O[MM * EE];
__device__ float g_X1[MM * EE];
__device__ float g_X2[MM * EE];
__device__ float g_H[MM * FF];

// ---------------------------------------------------------------------------
// SGEMM: C[M,N] = A[M,K] @ W[N,K]^T + bias, optional ReLU
// 128x128 block tile, BK=16, 256 threads, 8x8 per-thread micro-tile
// ---------------------------------------------------------------------------
template <bool RELU>
__global__ __launch_bounds__(256) void sgemm_bias_kernel(
    const float* __restrict__ A, const float* __restrict__ W,
    const float* __restrict__ bias, float* __restrict__ C,
    int M, int N, int K)
{
    __shared__ float As[16][132];
    __shared__ float Ws[16][132];

    const int tid = threadIdx.x;
    const int tx = tid & 15;       // 0..15 -> n micro
    const int ty = tid >> 4;       // 0..15 -> m micro
    const int m0 = blockIdx.y * 128;
    const int n0 = blockIdx.x * 128;

    float acc[8][8];
#pragma unroll
    for (int i = 0; i < 8; i++)
#pragma unroll
        for (int j = 0; j < 8; j++) acc[i][j] = 0.0f;

    for (int k0 = 0; k0 < K; k0 += 16) {
#pragma unroll
        for (int it = 0; it < 2; it++) {
            int f = tid + it * 256;        // 0..511
            int row = f >> 2;              // 0..127
            int c4 = (f & 3) * 4;          // 0,4,8,12
            float4 va = *reinterpret_cast<const float4*>(
                &A[(size_t)(m0 + row) * K + k0 + c4]);
            As[c4 + 0][row] = va.x; As[c4 + 1][row] = va.y;
            As[c4 + 2][row] = va.z; As[c4 + 3][row] = va.w;
            float4 vw = *reinterpret_cast<const float4*>(
                &W[(size_t)(n0 + row) * K + k0 + c4]);
            Ws[c4 + 0][row] = vw.x; Ws[c4 + 1][row] = vw.y;
            Ws[c4 + 2][row] = vw.z; Ws[c4 + 3][row] = vw.w;
        }
        __syncthreads();

#pragma unroll
        for (int k = 0; k < 16; k++) {
            float a[8], b[8];
            *reinterpret_cast<float4*>(&a[0]) =
                *reinterpret_cast<const float4*>(&As[k][ty * 8]);
            *reinterpret_cast<float4*>(&a[4]) =
                *reinterpret_cast<const float4*>(&As[k][ty * 8 + 4]);
            *reinterpret_cast<float4*>(&b[0]) =
                *reinterpret_cast<const float4*>(&Ws[k][tx * 8]);
            *reinterpret_cast<float4*>(&b[4]) =
                *reinterpret_cast<const float4*>(&Ws[k][tx * 8 + 4]);
#pragma unroll
            for (int i = 0; i < 8; i++)
#pragma unroll
                for (int j = 0; j < 8; j++)
                    acc[i][j] = fmaf(a[i], b[j], acc[i][j]);
        }
        __syncthreads();
    }

#pragma unroll
    for (int i = 0; i < 8; i++) {
        int m = m0 + ty * 8 + i;
#pragma unroll
        for (int j = 0; j < 8; j += 4) {
            int n = n0 + tx * 8 + j;
            float4 r;
            r.x = acc[i][j + 0] + bias[n + 0];
            r.y = acc[i][j + 1] + bias[n + 1];
            r.z = acc[i][j + 2] + bias[n + 2];
            r.w = acc[i][j + 3] + bias[n + 3];
            if (RELU) {
                r.x = fmaxf(r.x, 0.0f); r.y = fmaxf(r.y, 0.0f);
                r.z = fmaxf(r.z, 0.0f); r.w = fmaxf(r.w, 0.0f);
            }
            *reinterpret_cast<float4*>(&C[(size_t)m * N + n]) = r;
        }
    }
}

// ---------------------------------------------------------------------------
// Flash attention (fp32). Q,K,V,O are [rows, E] with row = token*B + b,
// channel = h*HD + d. grid = (L/64, H, B), block = 256 threads.
// Each block: 64 queries, streams key tiles of 64 with online softmax.
// Thread (ty,tx) owns rows ty*4..+3, cols/dims tx*4..+3.
// ---------------------------------------------------------------------------
#define FPAD 68
__global__ __launch_bounds__(256) void flash_attn_kernel(
    const float* __restrict__ Q, const float* __restrict__ K,
    const float* __restrict__ V, float* __restrict__ O,
    int Lk, int causal)
{
    extern __shared__ float sm[];
    float (*Qs)[FPAD] = reinterpret_cast<float(*)[FPAD]>(sm);
    float (*Ks)[FPAD] = reinterpret_cast<float(*)[FPAD]>(sm + 64 * FPAD);
    float (*Vs)[FPAD] = reinterpret_cast<float(*)[FPAD]>(sm + 2 * 64 * FPAD);

    const int tid = threadIdx.x;
    const int tx = tid & 15;
    const int ty = tid >> 4;
    const int qb = blockIdx.x;
    const int h = blockIdx.y;
    const int b = blockIdx.z;
    const float scale = 0.125f;  // 1/sqrt(64)

    // Load Q tile [64 x 64]
#pragma unroll
    for (int it = 0; it < 4; it++) {
        int f = tid + it * 256;            // 0..1023
        int row = f >> 4;                  // 0..63
        int c4 = (f & 15) * 4;             // 0..60
        int gq = qb * 64 + row;
        float4 v = *reinterpret_cast<const float4*>(
            &Q[((size_t)gq * BB + b) * EE + h * HD + c4]);
        *reinterpret_cast<float4*>(&Qs[row][c4]) = v;
    }

    float m_i[4], l_i[4], acc[4][4];
#pragma unroll
    for (int i = 0; i < 4; i++) {
        m_i[i] = -1e30f; l_i[i] = 0.0f;
#pragma unroll
        for (int j = 0; j < 4; j++) acc[i][j] = 0.0f;
    }

    const int nkt = causal ? (qb + 1) : (Lk / 64);

    for (int kt = 0; kt < nkt; kt++) {
        __syncthreads();  // prior PV reads of Ks/Vs done (also publishes Qs)
#pragma unroll
        for (int it = 0; it < 4; it++) {
            int f = tid + it * 256;
            int row = f >> 4;
            int c4 = (f & 15) * 4;
            int gk = kt * 64 + row;
            size_t base = ((size_t)gk * BB + b) * EE + h * HD + c4;
            *reinterpret_cast<float4*>(&Ks[row][c4]) =
                *reinterpret_cast<const float4*>(&K[base]);
            *reinterpret_cast<float4*>(&Vs[row][c4]) =
                *reinterpret_cast<const float4*>(&V[base]);
        }
        __syncthreads();

        // Scores S = Q K^T (4x4 per thread)
        float s[4][4];
#pragma unroll
        for (int i = 0; i < 4; i++)
#pragma unroll
            for (int j = 0; j < 4; j++) s[i][j] = 0.0f;

#pragma unroll
        for (int d4 = 0; d4 < 16; d4++) {
            float4 a4[4], b4[4];
#pragma unroll
            for (int i = 0; i < 4; i++)
                a4[i] = *reinterpret_cast<const float4*>(&Qs[ty * 4 + i][d4 * 4]);
#pragma unroll
            for (int j = 0; j < 4; j++)
                b4[j] = *reinterpret_cast<const float4*>(&Ks[tx * 4 + j][d4 * 4]);
#pragma unroll
            for (int i = 0; i < 4; i++)
#pragma unroll
                for (int j = 0; j < 4; j++) {
                    s[i][j] = fmaf(a4[i].x, b4[j].x, s[i][j]);
                    s[i][j] = fmaf(a4[i].y, b4[j].y, s[i][j]);
                    s[i][j] = fmaf(a4[i].z, b4[j].z, s[i][j]);
                    s[i][j] = fmaf(a4[i].w, b4[j].w, s[i][j]);
                }
        }

        // Scale + causal mask
#pragma unroll
        for (int i = 0; i < 4; i++) {
            int qi = qb * 64 + ty * 4 + i;
#pragma unroll
            for (int j = 0; j < 4; j++) {
                s[i][j] *= scale;
                int kj = kt * 64 + tx * 4 + j;
                if (causal && kj > qi) s[i][j] = -1e30f;
            }
        }

        // Online softmax update
        float p[4][4];
#pragma unroll
        for (int i = 0; i < 4; i++) {
            float rmax = fmaxf(fmaxf(s[i][0], s[i][1]), fmaxf(s[i][2], s[i][3]));
#pragma unroll
            for (int off = 1; off < 16; off <<= 1)
                rmax = fmaxf(rmax, __shfl_xor_sync(0xffffffffu, rmax, off));
            float newm = fmaxf(m_i[i], rmax);
            float corr = __expf(m_i[i] - newm);
            m_i[i] = newm;
            float rsum = 0.0f;
#pragma unroll
            for (int j = 0; j < 4; j++) {
                p[i][j] = __expf(s[i][j] - newm);
                rsum += p[i][j];
            }
#pragma unroll
            for (int off = 1; off < 16; off <<= 1)
                rsum += __shfl_xor_sync(0xffffffffu, rsum, off);
            l_i[i] = l_i[i] * corr + rsum;
#pragma unroll
            for (int j = 0; j < 4; j++) acc[i][j] *= corr;
        }

        // Write P into Ks storage (K no longer needed this tile)
        __syncthreads();
#pragma unroll
        for (int i = 0; i < 4; i++) {
            float4 pv = make_float4(p[i][0], p[i][1], p[i][2], p[i][3]);
            *reinterpret_cast<float4*>(&Ks[ty * 4 + i][tx * 4]) = pv;
        }
        __syncthreads();

        // acc += P @ V
#pragma unroll 8
        for (int n = 0; n < 64; n++) {
            float4 bv = *reinterpret_cast<const float4*>(&Vs[n][tx * 4]);
#pragma unroll
            for (int i = 0; i < 4; i++) {
                float av = Ks[ty * 4 + i][n];
                acc[i][0] = fmaf(av, bv.x, acc[i][0]);
                acc[i][1] = fmaf(av, bv.y, acc[i][1]);
                acc[i][2] = fmaf(av, bv.z, acc[i][2]);
                acc[i][3] = fmaf(av, bv.w, acc[i][3]);
            }
        }
    }

    // Normalize + store
#pragma unroll
    for (int i = 0; i < 4; i++) {
        float inv = 1.0f / l_i[i];
        int gq = qb * 64 + ty * 4 + i;
        float4 r = make_float4(acc[i][0] * inv, acc[i][1] * inv,
                               acc[i][2] * inv, acc[i][3] * inv);
        *reinterpret_cast<float4*>(
            &O[((size_t)gq * BB + b) * EE + h * HD + tx * 4]) = r;
    }
}

// ---------------------------------------------------------------------------
// Fused add + LayerNorm: out = LN(x + y) * g + b   (row length = 1024)
// One block per row, 256 threads, 4 floats/thread.
// ---------------------------------------------------------------------------
__global__ __launch_bounds__(256) void add_ln_kernel(
    const float* __restrict__ X, const float* __restrict__ Y,
    const float* __restrict__ gamma, const float* __restrict__ beta,
    float* __restrict__ out)
{
    const int row = blockIdx.x;
    const int tid = threadIdx.x;
    const size_t base = (size_t)row * EE + tid * 4;

    float4 xv = *reinterpret_cast<const float4*>(&X[base]);
    float4 yv = *reinterpret_cast<const float4*>(&Y[base]);
    float v0 = xv.x + yv.x, v1 = xv.y + yv.y, v2 = xv.z + yv.z, v3 = xv.w + yv.w;

    float s1 = v0 + v1 + v2 + v3;
    float s2 = v0 * v0 + v1 * v1 + v2 * v2 + v3 * v3;

    // block reduce (8 warps)
    __shared__ float sm1[8], sm2[8];
#pragma unroll
    for (int off = 16; off > 0; off >>= 1) {
        s1 += __shfl_xor_sync(0xffffffffu, s1, off);
        s2 += __shfl_xor_sync(0xffffffffu, s2, off);
    }
    int wid = tid >> 5, lid = tid & 31;
    if (lid == 0) { sm1[wid] = s1; sm2[wid] = s2; }
    __syncthreads();
    if (wid == 0) {
        s1 = (lid < 8) ? sm1[lid] : 0.0f;
        s2 = (lid < 8) ? sm2[lid] : 0.0f;
#pragma unroll
        for (int off = 4; off > 0; off >>= 1) {
            s1 += __shfl_xor_sync(0xffffffffu, s1, off);
            s2 += __shfl_xor_sync(0xffffffffu, s2, off);
        }
        if (lid == 0) { sm1[0] = s1; sm2[0] = s2; }
    }
    __syncthreads();
    float mean = sm1[0] * (1.0f / EE);
    float var = sm2[0] * (1.0f / EE) - mean * mean;
    float r = rsqrtf(var + 1e-5f);

    int c = tid * 4;
    float4 gv = *reinterpret_cast<const float4*>(&gamma[c]);
    float4 bv = *reinterpret_cast<const float4*>(&beta[c]);
    float4 o;
    o.x = (v0 - mean) * r * gv.x + bv.x;
    o.y = (v1 - mean) * r * gv.y + bv.y;
    o.z = (v2 - mean) * r * gv.z + bv.z;
    o.w = (v3 - mean) * r * gv.w + bv.w;
    *reinterpret_cast<float4*>(&out[base]) = o;
}

// ---------------------------------------------------------------------------
// Host orchestration
// ---------------------------------------------------------------------------
static void launch_gemm(const float* A, const float* W, const float* bias,
                        float* C, int M, int N, int K, bool relu)
{
    dim3 grid(N / 128, M / 128);
    if (relu)
        sgemm_bias_kernel<true><<<grid, 256>>>(A, W, bias, C, M, N, K);
    else
        sgemm_bias_kernel<false><<<grid, 256>>>(A, W, bias, C, M, N, K);
}

extern "C" void kernel_launch(void* const* d_in, const int* in_sizes, int n_in,
                              void* d_out, int out_size)
{
    const float* tgt    = (const float*)d_in[0];
    const float* memory = (const float*)d_in[1];
    // d_in[2] = tgt_mask (causal; implemented directly)
    const float* sa_Wq = (const float*)d_in[3];
    const float* sa_bq = (const float*)d_in[4];
    const float* sa_Wk = (const float*)d_in[5];
    const float* sa_bk = (const float*)d_in[6];
    const float* sa_Wv = (const float*)d_in[7];
    const float* sa_bv = (const float*)d_in[8];
    const float* sa_Wo = (const float*)d_in[9];
    const float* sa_bo = (const float*)d_in[10];
    const float* ca_Wq = (const float*)d_in[11];
    const float* ca_bq = (const float*)d_in[12];
    const float* ca_Wk = (const float*)d_in[13];
    const float* ca_bk = (const float*)d_in[14];
    const float* ca_Wv = (const float*)d_in[15];
    const float* ca_bv = (const float*)d_in[16];
    const float* ca_Wo = (const float*)d_in[17];
    const float* ca_bo = (const float*)d_in[18];
    const float* W1    = (const float*)d_in[19];
    const float* b1    = (const float*)d_in[20];
    const float* W2    = (const float*)d_in[21];
    const float* b2    = (const float*)d_in[22];
    const float* ln1_g = (const float*)d_in[23];
    const float* ln1_b = (const float*)d_in[24];
    const float* ln2_g = (const float*)d_in[25];
    const float* ln2_b = (const float*)d_in[26];
    const float* ln3_g = (const float*)d_in[27];
    const float* ln3_b = (const float*)d_in[28];
    float* out = (float*)d_out;

    float *pQ, *pK, *pV, *pA, *pO, *pX1, *pX2, *pH;
    cudaGetSymbolAddress((void**)&pQ, g_Q);
    cudaGetSymbolAddress((void**)&pK, g_K);
    cudaGetSymbolAddress((void**)&pV, g_V);
    cudaGetSymbolAddress((void**)&pA, g_A);
    cudaGetSymbolAddress((void**)&pO, g_O);
    cudaGetSymbolAddress((void**)&pX1, g_X1);
    cudaGetSymbolAddress((void**)&pX2, g_X2);
    cudaGetSymbolAddress((void**)&pH, g_H);

    const int FLASH_SMEM = 3 * 64 * FPAD * (int)sizeof(float);  // 52224 B
    cudaFuncSetAttribute(flash_attn_kernel,
                         cudaFuncAttributeMaxDynamicSharedMemorySize, FLASH_SMEM);

    dim3 attn_grid(LQ / 64, HH, BB);

    // ---- Self-attention block ----
    launch_gemm(tgt, sa_Wq, sa_bq, pQ, MM, EE, EE, false);
    launch_gemm(tgt, sa_Wk, sa_bk, pK, MM, EE, EE, false);
    launch_gemm(tgt, sa_Wv, sa_bv, pV, MM, EE, EE, false);
    flash_attn_kernel<<<attn_grid, 256, FLASH_SMEM>>>(pQ, pK, pV, pA, SK, 1);
    launch_gemm(pA, sa_Wo, sa_bo, pO, MM, EE, EE, false);
    add_ln_kernel<<<MM, 256>>>(tgt, pO, ln1_g, ln1_b, pX1);

    // ---- Cross-attention block ----
    launch_gemm(pX1, ca_Wq, ca_bq, pQ, MM, EE, EE, false);
    launch_gemm(memory, ca_Wk, ca_bk, pK, MM, EE, EE, false);
    launch_gemm(memory, ca_Wv, ca_bv, pV, MM, EE, EE, false);
    flash_attn_kernel<<<attn_grid, 256, FLASH_SMEM>>>(pQ, pK, pV, pA, SK, 0);
    launch_gemm(pA, ca_Wo, ca_bo, pO, MM, EE, EE, false);
    add_ln_kernel<<<MM, 256>>>(pX1, pO, ln2_g, ln2_b, pX2);

    // ---- FFN block ----
    launch_gemm(pX2, W1, b1, pH, MM, FF, EE, true);   // ReLU fused
    launch_gemm(pH, W2, b2, pO, MM, EE, FF, false);
    add_ln_kernel<<<MM, 256>>>(pX2, pO, ln3_g, ln3_b, out);
}

// round 2
// speedup vs baseline: 3.3353x; 3.3353x over previous
#include <cuda_runtime.h>
#include <cuda_bf16.h>
#include <cstdint>

// Problem constants
#define LQ 2048
#define SK 2048
#define BB 4
#define EE 1024
#define HH 16
#define HD 64
#define FF 4096
#define MM (LQ * BB)   // 8192 rows

// ---------------------------------------------------------------------------
// Scratch buffers (__device__ globals: allocation-free per harness rules)
// ---------------------------------------------------------------------------
__device__ float g_Q[MM * EE];
__device__ float g_K[MM * EE];
__device__ float g_V[MM * EE];
__device__ float g_A[MM * EE];
__device__ float g_O[MM * EE];
__device__ float g_X1[MM * EE];
__device__ float g_X2[MM * EE];
__device__ float g_H[MM * FF];

// ---------------------------------------------------------------------------
// Helpers
// ---------------------------------------------------------------------------
__device__ __forceinline__ unsigned f2tf32(float x) {
    unsigned r;
    asm("cvt.rna.tf32.f32 %0, %1;" : "=r"(r) : "f"(x));
    return r;
}

__device__ __forceinline__ void mma_tf32(float* c, const unsigned* a, const unsigned* b) {
    asm volatile(
        "mma.sync.aligned.m16n8k8.row.col.f32.tf32.tf32.f32 "
        "{%0,%1,%2,%3}, {%4,%5,%6,%7}, {%8,%9}, {%0,%1,%2,%3};\n"
        : "+f"(c[0]), "+f"(c[1]), "+f"(c[2]), "+f"(c[3])
        : "r"(a[0]), "r"(a[1]), "r"(a[2]), "r"(a[3]), "r"(b[0]), "r"(b[1]));
}

// ---------------------------------------------------------------------------
// TF32 tensor-core GEMM: C[M,N] = A[M,K] @ W[N,K]^T + bias, optional ReLU
// Block tile 128x128, BK=32, 256 threads = 8 warps (2x4), warp tile 64x32.
// Smem row stride 36 (== 4 mod 32) -> fragment loads are conflict-free.
// ---------------------------------------------------------------------------
#define GPAD 36
template <bool RELU>
__global__ __launch_bounds__(256, 2) void gemm_tf32_kernel(
    const float* __restrict__ A, const float* __restrict__ W,
    const float* __restrict__ bias, float* __restrict__ C,
    int M, int N, int K)
{
    __shared__ unsigned As[128 * GPAD];
    __shared__ unsigned Ws[128 * GPAD];

    const int tid = threadIdx.x;
    const int lane = tid & 31;
    const int wid = tid >> 5;
    const int wm = wid >> 2;        // 0..1
    const int wn = wid & 3;         // 0..3
    const int g = lane >> 2;        // groupID 0..7
    const int t4 = lane & 3;        // threadID in group

    const int m0 = blockIdx.y * 128;
    const int n0 = blockIdx.x * 128;

    float acc[4][4][4];
#pragma unroll
    for (int mt = 0; mt < 4; mt++)
#pragma unroll
        for (int nt = 0; nt < 4; nt++)
#pragma unroll
            for (int r = 0; r < 4; r++) acc[mt][nt][r] = 0.0f;

    const int lrow = tid >> 3;           // 0..31 base row per iter set
    const int lc4 = (tid & 7) * 4;       // 0..28

    for (int k0 = 0; k0 < K; k0 += 32) {
        // Load 128x32 tiles of A and W, converting fp32 -> tf32
#pragma unroll
        for (int it = 0; it < 4; it++) {
            int row = lrow + it * 32;
            float4 va = *reinterpret_cast<const float4*>(
                &A[(size_t)(m0 + row) * K + k0 + lc4]);
            uint4 ua = make_uint4(f2tf32(va.x), f2tf32(va.y), f2tf32(va.z), f2tf32(va.w));
            *reinterpret_cast<uint4*>(&As[row * GPAD + lc4]) = ua;
            float4 vw = *reinterpret_cast<const float4*>(
                &W[(size_t)(n0 + row) * K + k0 + lc4]);
            uint4 uw = make_uint4(f2tf32(vw.x), f2tf32(vw.y), f2tf32(vw.z), f2tf32(vw.w));
            *reinterpret_cast<uint4*>(&Ws[row * GPAD + lc4]) = uw;
        }
        __syncthreads();

#pragma unroll
        for (int ks = 0; ks < 4; ks++) {
            const int kk = ks * 8;
            unsigned a[4][4], b[4][2];
#pragma unroll
            for (int mt = 0; mt < 4; mt++) {
                int r = wm * 64 + mt * 16 + g;
                a[mt][0] = As[r * GPAD + kk + t4];
                a[mt][1] = As[(r + 8) * GPAD + kk + t4];
                a[mt][2] = As[r * GPAD + kk + t4 + 4];
                a[mt][3] = As[(r + 8) * GPAD + kk + t4 + 4];
            }
#pragma unroll
            for (int nt = 0; nt < 4; nt++) {
                int c = wn * 32 + nt * 8 + g;
                b[nt][0] = Ws[c * GPAD + kk + t4];
                b[nt][1] = Ws[c * GPAD + kk + t4 + 4];
            }
#pragma unroll
            for (int mt = 0; mt < 4; mt++)
#pragma unroll
                for (int nt = 0; nt < 4; nt++)
                    mma_tf32(acc[mt][nt], a[mt], b[nt]);
        }
        __syncthreads();
    }

    // Epilogue: bias (+ReLU) and store
#pragma unroll
    for (int mt = 0; mt < 4; mt++) {
        int row0 = m0 + wm * 64 + mt * 16 + g;
#pragma unroll
        for (int nt = 0; nt < 4; nt++) {
            int col = n0 + wn * 32 + nt * 8 + 2 * t4;
            float b0 = bias[col], b1 = bias[col + 1];
            float v0 = acc[mt][nt][0] + b0;
            float v1 = acc[mt][nt][1] + b1;
            float v2 = acc[mt][nt][2] + b0;
            float v3 = acc[mt][nt][3] + b1;
            if (RELU) {
                v0 = fmaxf(v0, 0.0f); v1 = fmaxf(v1, 0.0f);
                v2 = fmaxf(v2, 0.0f); v3 = fmaxf(v3, 0.0f);
            }
            *reinterpret_cast<float2*>(&C[(size_t)row0 * N + col]) = make_float2(v0, v1);
            *reinterpret_cast<float2*>(&C[(size_t)(row0 + 8) * N + col]) = make_float2(v2, v3);
        }
    }
}

// ---------------------------------------------------------------------------
// Flash attention, TF32 tensor cores.
// Q,K,V,O are [rows, E] with row = token*B + b, channel = h*HD + d.
// grid = (L/64, H, B), block = 128 threads (4 warps).
// Each block: 64 queries; streams 64-key tiles with online softmax.
// Warp w owns query rows [16w, 16w+16).
// ---------------------------------------------------------------------------
#define APAD 68
__global__ __launch_bounds__(128) void flash_attn_tc_kernel(
    const float* __restrict__ Q, const float* __restrict__ K,
    const float* __restrict__ V, float* __restrict__ O,
    int causal)
{
    extern __shared__ unsigned smu[];
    unsigned* Qs = smu;
    unsigned* Ks = smu + 64 * APAD;
    unsigned* Vs = smu + 2 * 64 * APAD;
    unsigned* Ps = smu + 3 * 64 * APAD;

    const int tid = threadIdx.x;
    const int lane = tid & 31;
    const int wid = tid >> 5;
    const int g = lane >> 2;
    const int t4 = lane & 3;
    const int qr = wid * 16;       // warp's query-row base within tile

    const int qb = blockIdx.x;
    const int h = blockIdx.y;
    const int b = blockIdx.z;
    const float scale = 0.125f;    // 1/sqrt(64)

    // Load Q tile [64 x 64], pre-scaled, tf32
#pragma unroll
    for (int it = 0; it < 8; it++) {
        int f = tid + it * 128;
        int row = f >> 4;
        int c4 = (f & 15) * 4;
        float4 v = *reinterpret_cast<const float4*>(
            &Q[((size_t)(qb * 64 + row) * BB + b) * EE + h * HD + c4]);
        uint4 u = make_uint4(f2tf32(v.x * scale), f2tf32(v.y * scale),
                             f2tf32(v.z * scale), f2tf32(v.w * scale));
        *reinterpret_cast<uint4*>(&Qs[row * APAD + c4]) = u;
    }

    float o[8][4];
#pragma unroll
    for (int nt = 0; nt < 8; nt++)
#pragma unroll
        for (int r = 0; r < 4; r++) o[nt][r] = 0.0f;
    float m0_ = -1e30f, m1_ = -1e30f, l0_ = 0.0f, l1_ = 0.0f;

    const int nkt = causal ? (qb + 1) : (SK / 64);

    for (int kt = 0; kt < nkt; kt++) {
        __syncthreads();  // prior PV done; Qs published on first iter
#pragma unroll
        for (int it = 0; it < 8; it++) {
            int f = tid + it * 128;
            int row = f >> 4;
            int c4 = (f & 15) * 4;
            size_t base = ((size_t)(kt * 64 + row) * BB + b) * EE + h * HD + c4;
            float4 kv = *reinterpret_cast<const float4*>(&K[base]);
            *reinterpret_cast<uint4*>(&Ks[row * APAD + c4]) =
                make_uint4(f2tf32(kv.x), f2tf32(kv.y), f2tf32(kv.z), f2tf32(kv.w));
            float4 vv = *reinterpret_cast<const float4*>(&V[base]);
            *reinterpret_cast<uint4*>(&Vs[row * APAD + c4]) =
                make_uint4(f2tf32(vv.x), f2tf32(vv.y), f2tf32(vv.z), f2tf32(vv.w));
        }
        __syncthreads();

        // S = Q K^T  (warp: m16 x n64, k=64)
        float s[8][4];
#pragma unroll
        for (int nt = 0; nt < 8; nt++)
#pragma unroll
            for (int r = 0; r < 4; r++) s[nt][r] = 0.0f;

#pragma unroll
        for (int ks = 0; ks < 8; ks++) {
            const int kk = ks * 8;
            unsigned a[4];
            a[0] = Qs[(qr + g) * APAD + kk + t4];
            a[1] = Qs[(qr + g + 8) * APAD + kk + t4];
            a[2] = Qs[(qr + g) * APAD + kk + t4 + 4];
            a[3] = Qs[(qr + g + 8) * APAD + kk + t4 + 4];
#pragma unroll
            for (int nt = 0; nt < 8; nt++) {
                unsigned bfr[2];
                bfr[0] = Ks[(nt * 8 + g) * APAD + kk + t4];
                bfr[1] = Ks[(nt * 8 + g) * APAD + kk + t4 + 4];
                mma_tf32(s[nt], a, bfr);
            }
        }

        // Causal mask: only the diagonal tile needs per-element masking
        if (causal && kt == qb) {
            int row0 = qb * 64 + qr + g;
            int row1 = row0 + 8;
#pragma unroll
            for (int nt = 0; nt < 8; nt++) {
                int col = kt * 64 + nt * 8 + 2 * t4;
                if (col > row0)     s[nt][0] = -1e30f;
                if (col + 1 > row0) s[nt][1] = -1e30f;
                if (col > row1)     s[nt][2] = -1e30f;
                if (col + 1 > row1) s[nt][3] = -1e30f;
            }
        }

        // Online softmax (thread owns rows g and g+8 of the warp's m16)
        float mx0 = -1e30f, mx1 = -1e30f;
#pragma unroll
        for (int nt = 0; nt < 8; nt++) {
            mx0 = fmaxf(mx0, fmaxf(s[nt][0], s[nt][1]));
            mx1 = fmaxf(mx1, fmaxf(s[nt][2], s[nt][3]));
        }
        mx0 = fmaxf(mx0, __shfl_xor_sync(0xffffffffu, mx0, 1));
        mx0 = fmaxf(mx0, __shfl_xor_sync(0xffffffffu, mx0, 2));
        mx1 = fmaxf(mx1, __shfl_xor_sync(0xffffffffu, mx1, 1));
        mx1 = fmaxf(mx1, __shfl_xor_sync(0xffffffffu, mx1, 2));

        float nm0 = fmaxf(m0_, mx0);
        float nm1 = fmaxf(m1_, mx1);
        float corr0 = __expf(m0_ - nm0);
        float corr1 = __expf(m1_ - nm1);
        m0_ = nm0; m1_ = nm1;

        float sum0 = 0.0f, sum1 = 0.0f;
#pragma unroll
        for (int nt = 0; nt < 8; nt++) {
            s[nt][0] = __expf(s[nt][0] - nm0);
            s[nt][1] = __expf(s[nt][1] - nm0);
            s[nt][2] = __expf(s[nt][2] - nm1);
            s[nt][3] = __expf(s[nt][3] - nm1);
            sum0 += s[nt][0] + s[nt][1];
            sum1 += s[nt][2] + s[nt][3];
        }
        sum0 += __shfl_xor_sync(0xffffffffu, sum0, 1);
        sum0 += __shfl_xor_sync(0xffffffffu, sum0, 2);
        sum1 += __shfl_xor_sync(0xffffffffu, sum1, 1);
        sum1 += __shfl_xor_sync(0xffffffffu, sum1, 2);
        l0_ = l0_ * corr0 + sum0;
        l1_ = l1_ * corr1 + sum1;
#pragma unroll
        for (int nt = 0; nt < 8; nt++) {
            o[nt][0] *= corr0; o[nt][1] *= corr0;
            o[nt][2] *= corr1; o[nt][3] *= corr1;
        }

        // Store P (tf32) to smem for use as the A operand of PV
#pragma unroll
        for (int nt = 0; nt < 8; nt++) {
            *reinterpret_cast<uint2*>(&Ps[(qr + g) * APAD + nt * 8 + 2 * t4]) =
                make_uint2(f2tf32(s[nt][0]), f2tf32(s[nt][1]));
            *reinterpret_cast<uint2*>(&Ps[(qr + g + 8) * APAD + nt * 8 + 2 * t4]) =
                make_uint2(f2tf32(s[nt][2]), f2tf32(s[nt][3]));
        }
        __syncthreads();

        // O += P @ V   (warp: m16 x n64, k = 64 keys)
#pragma unroll
        for (int ks = 0; ks < 8; ks++) {
            const int kk = ks * 8;
            unsigned a[4];
            a[0] = Ps[(qr + g) * APAD + kk + t4];
            a[1] = Ps[(qr + g + 8) * APAD + kk + t4];
            a[2] = Ps[(qr + g) * APAD + kk + t4 + 4];
            a[3] = Ps[(qr + g + 8) * APAD + kk + t4 + 4];
#pragma unroll
            for (int nt = 0; nt < 8; nt++) {
                unsigned bfr[2];
                bfr[0] = Vs[(kk + t4) * APAD + nt * 8 + g];
                bfr[1] = Vs[(kk + t4 + 4) * APAD + nt * 8 + g];
                mma_tf32(o[nt], a, bfr);
            }
        }
    }

    // Normalize + store
    float inv0 = 1.0f / l0_;
    float inv1 = 1.0f / l1_;
    int tok0 = qb * 64 + qr + g;
#pragma unroll
    for (int nt = 0; nt < 8; nt++) {
        int col = h * HD + nt * 8 + 2 * t4;
        *reinterpret_cast<float2*>(&O[((size_t)tok0 * BB + b) * EE + col]) =
            make_float2(o[nt][0] * inv0, o[nt][1] * inv0);
        *reinterpret_cast<float2*>(&O[((size_t)(tok0 + 8) * BB + b) * EE + col]) =
            make_float2(o[nt][2] * inv1, o[nt][3] * inv1);
    }
}

// ---------------------------------------------------------------------------
// Fused add + LayerNorm: out = LN(x + y) * g + b   (row length = 1024)
// ---------------------------------------------------------------------------
__global__ __launch_bounds__(256) void add_ln_kernel(
    const float* __restrict__ X, const float* __restrict__ Y,
    const float* __restrict__ gamma, const float* __restrict__ beta,
    float* __restrict__ out)
{
    const int row = blockIdx.x;
    const int tid = threadIdx.x;
    const size_t base = (size_t)row * EE + tid * 4;

    float4 xv = *reinterpret_cast<const float4*>(&X[base]);
    float4 yv = *reinterpret_cast<const float4*>(&Y[base]);
    float v0 = xv.x + yv.x, v1 = xv.y + yv.y, v2 = xv.z + yv.z, v3 = xv.w + yv.w;

    float s1 = v0 + v1 + v2 + v3;
    float s2 = v0 * v0 + v1 * v1 + v2 * v2 + v3 * v3;

    __shared__ float sm1[8], sm2[8];
#pragma unroll
    for (int off = 16; off > 0; off >>= 1) {
        s1 += __shfl_xor_sync(0xffffffffu, s1, off);
        s2 += __shfl_xor_sync(0xffffffffu, s2, off);
    }
    int wid = tid >> 5, lid = tid & 31;
    if (lid == 0) { sm1[wid] = s1; sm2[wid] = s2; }
    __syncthreads();
    if (wid == 0) {
        s1 = (lid < 8) ? sm1[lid] : 0.0f;
        s2 = (lid < 8) ? sm2[lid] : 0.0f;
#pragma unroll
        for (int off = 4; off > 0; off >>= 1) {
            s1 += __shfl_xor_sync(0xffffffffu, s1, off);
            s2 += __shfl_xor_sync(0xffffffffu, s2, off);
        }
        if (lid == 0) { sm1[0] = s1; sm2[0] = s2; }
    }
    __syncthreads();
    float mean = sm1[0] * (1.0f / EE);
    float var = sm2[0] * (1.0f / EE) - mean * mean;
    float r = rsqrtf(var + 1e-5f);

    int c = tid * 4;
    float4 gv = *reinterpret_cast<const float4*>(&gamma[c]);
    float4 bv = *reinterpret_cast<const float4*>(&beta[c]);
    float4 ov;
    ov.x = (v0 - mean) * r * gv.x + bv.x;
    ov.y = (v1 - mean) * r * gv.y + bv.y;
    ov.z = (v2 - mean) * r * gv.z + bv.z;
    ov.w = (v3 - mean) * r * gv.w + bv.w;
    *reinterpret_cast<float4*>(&out[base]) = ov;
}

// ---------------------------------------------------------------------------
// Host orchestration
// ---------------------------------------------------------------------------
static void launch_gemm(const float* A, const float* W, const float* bias,
                        float* C, int M, int N, int K, bool relu)
{
    dim3 grid(N / 128, M / 128);
    if (relu)
        gemm_tf32_kernel<true><<<grid, 256>>>(A, W, bias, C, M, N, K);
    else
        gemm_tf32_kernel<false><<<grid, 256>>>(A, W, bias, C, M, N, K);
}

extern "C" void kernel_launch(void* const* d_in, const int* in_sizes, int n_in,
                              void* d_out, int out_size)
{
    const float* tgt    = (const float*)d_in[0];
    const float* memory = (const float*)d_in[1];
    // d_in[2] = tgt_mask (causal; implemented directly)
    const float* sa_Wq = (const float*)d_in[3];
    const float* sa_bq = (const float*)d_in[4];
    const float* sa_Wk = (const float*)d_in[5];
    const float* sa_bk = (const float*)d_in[6];
    const float* sa_Wv = (const float*)d_in[7];
    const float* sa_bv = (const float*)d_in[8];
    const float* sa_Wo = (const float*)d_in[9];
    const float* sa_bo = (const float*)d_in[10];
    const float* ca_Wq = (const float*)d_in[11];
    const float* ca_bq = (const float*)d_in[12];
    const float* ca_Wk = (const float*)d_in[13];
    const float* ca_bk = (const float*)d_in[14];
    const float* ca_Wv = (const float*)d_in[15];
    const float* ca_bv = (const float*)d_in[16];
    const float* ca_Wo = (const float*)d_in[17];
    const float* ca_bo = (const float*)d_in[18];
    const float* W1    = (const float*)d_in[19];
    const float* b1    = (const float*)d_in[20];
    const float* W2    = (const float*)d_in[21];
    const float* b2    = (const float*)d_in[22];
    const float* ln1_g = (const float*)d_in[23];
    const float* ln1_b = (const float*)d_in[24];
    const float* ln2_g = (const float*)d_in[25];
    const float* ln2_b = (const float*)d_in[26];
    const float* ln3_g = (const float*)d_in[27];
    const float* ln3_b = (const float*)d_in[28];
    float* out = (float*)d_out;

    float *pQ, *pK, *pV, *pA, *pO, *pX1, *pX2, *pH;
    cudaGetSymbolAddress((void**)&pQ, g_Q);
    cudaGetSymbolAddress((void**)&pK, g_K);
    cudaGetSymbolAddress((void**)&pV, g_V);
    cudaGetSymbolAddress((void**)&pA, g_A);
    cudaGetSymbolAddress((void**)&pO, g_O);
    cudaGetSymbolAddress((void**)&pX1, g_X1);
    cudaGetSymbolAddress((void**)&pX2, g_X2);
    cudaGetSymbolAddress((void**)&pH, g_H);

    const int FLASH_SMEM = 4 * 64 * APAD * (int)sizeof(unsigned);  // 69632 B
    cudaFuncSetAttribute(flash_attn_tc_kernel,
                         cudaFuncAttributeMaxDynamicSharedMemorySize, FLASH_SMEM);

    dim3 attn_grid(LQ / 64, HH, BB);

    // ---- Self-attention block ----
    launch_gemm(tgt, sa_Wq, sa_bq, pQ, MM, EE, EE, false);
    launch_gemm(tgt, sa_Wk, sa_bk, pK, MM, EE, EE, false);
    launch_gemm(tgt, sa_Wv, sa_bv, pV, MM, EE, EE, false);
    flash_attn_tc_kernel<<<attn_grid, 128, FLASH_SMEM>>>(pQ, pK, pV, pA, 1);
    launch_gemm(pA, sa_Wo, sa_bo, pO, MM, EE, EE, false);
    add_ln_kernel<<<MM, 256>>>(tgt, pO, ln1_g, ln1_b, pX1);

    // ---- Cross-attention block ----
    launch_gemm(pX1, ca_Wq, ca_bq, pQ, MM, EE, EE, false);
    launch_gemm(memory, ca_Wk, ca_bk, pK, MM, EE, EE, false);
    launch_gemm(memory, ca_Wv, ca_bv, pV, MM, EE, EE, false);
    flash_attn_tc_kernel<<<attn_grid, 128, FLASH_SMEM>>>(pQ, pK, pV, pA, 0);
    launch_gemm(pA, ca_Wo, ca_bo, pO, MM, EE, EE, false);
    add_ln_kernel<<<MM, 256>>>(pX1, pO, ln2_g, ln2_b, pX2);

    // ---- FFN block ----
    launch_gemm(pX2, W1, b1, pH, MM, FF, EE, true);   // ReLU fused
    launch_gemm(pH, W2, b2, pO, MM, EE, FF, false);
    add_ln_kernel<<<MM, 256>>>(pX2, pO, ln3_g, ln3_b, out);
}

// round 4
// speedup vs baseline: 3.5267x; 1.0574x over previous
#include <cuda_runtime.h>
#include <cuda_bf16.h>
#include <cstdint>

// Problem constants
#define LQ 2048
#define SK 2048
#define BB 4
#define EE 1024
#define HH 16
#define HD 64
#define FF 4096
#define MM (LQ * BB)   // 8192 rows

// ---------------------------------------------------------------------------
// Scratch buffers (__device__ globals: allocation-free per harness rules)
// ---------------------------------------------------------------------------
__device__ float g_Q[MM * EE];
__device__ float g_K[MM * EE];
__device__ float g_V[MM * EE];
__device__ float g_A[MM * EE];
__device__ float g_O[MM * EE];
__device__ float g_X1[MM * EE];
__device__ float g_X2[MM * EE];
__device__ float g_H[MM * FF];

// ---------------------------------------------------------------------------
// Helpers
// ---------------------------------------------------------------------------
__device__ __forceinline__ unsigned f2tf32(float x) {
    unsigned r;
    asm("cvt.rna.tf32.f32 %0, %1;" : "=r"(r) : "f"(x));
    return r;
}

__device__ __forceinline__ void mma_tf32(float* c, const unsigned* a, const unsigned* b) {
    asm volatile(
        "mma.sync.aligned.m16n8k8.row.col.f32.tf32.tf32.f32 "
        "{%0,%1,%2,%3}, {%4,%5,%6,%7}, {%8,%9}, {%0,%1,%2,%3};\n"
        : "+f"(c[0]), "+f"(c[1]), "+f"(c[2]), "+f"(c[3])
        : "r"(a[0]), "r"(a[1]), "r"(a[2]), "r"(a[3]), "r"(b[0]), "r"(b[1]));
}

__device__ __forceinline__ void cp_async16(void* dst, const void* src) {
    unsigned d = (unsigned)__cvta_generic_to_shared(dst);
    asm volatile("cp.async.cg.shared.global [%0], [%1], 16;\n" :: "r"(d), "l"(src));
}

// ---------------------------------------------------------------------------
// TF32 tensor-core GEMM with cp.async double-buffered pipeline.
// C[M,N] = A[M,K] @ W[N,K]^T + bias, optional ReLU.
// Block tile 128x128, BK=32, 256 threads = 8 warps (2x4), warp tile 64x32.
// Smem holds raw fp32 (copied by LDGSTS); cvt.rna.tf32 at fragment load.
// Smem row stride 36 (== 4 mod 32) -> conflict-free fragment loads.
// ---------------------------------------------------------------------------
#define GPAD 36
#define GEMM_STAGE (128 * GPAD)
#define GEMM_SMEM (4 * GEMM_STAGE * 4)   // 2 stages x (A + W) tiles, bytes

template <bool RELU>
__global__ __launch_bounds__(256, 2) void gemm_tf32_kernel(
    const float* __restrict__ A, const float* __restrict__ W,
    const float* __restrict__ bias, float* __restrict__ C,
    int M, int N, int K)
{
    extern __shared__ float gsm[];
    float* AsBuf = gsm;                     // [2][128*GPAD]
    float* WsBuf = gsm + 2 * GEMM_STAGE;    // [2][128*GPAD]

    const int tid = threadIdx.x;
    const int lane = tid & 31;
    const int wid = tid >> 5;
    const int wm = wid >> 2;        // 0..1
    const int wn = wid & 3;         // 0..3
    const int g = lane >> 2;        // 0..7
    const int t4 = lane & 3;        // 0..3

    const int m0 = blockIdx.y * 128;
    const int n0 = blockIdx.x * 128;

    const int lrow = tid >> 3;           // 0..31
    const int lc4 = (tid & 7) * 4;       // 0,4,...,28

    const float* Ag = A + (size_t)(m0 + lrow) * K + lc4;
    const float* Wg = W + (size_t)(n0 + lrow) * K + lc4;

    float acc[4][4][4];
#pragma unroll
    for (int mt = 0; mt < 4; mt++)
#pragma unroll
        for (int nt = 0; nt < 4; nt++)
#pragma unroll
            for (int r = 0; r < 4; r++) acc[mt][nt][r] = 0.0f;

    auto load_stage = [&](int st, int kb) {
        float* as = AsBuf + st * GEMM_STAGE;
        float* ws = WsBuf + st * GEMM_STAGE;
        const float* ag = Ag + kb * 32;
        const float* wg = Wg + kb * 32;
#pragma unroll
        for (int it = 0; it < 4; it++) {
            int row = lrow + it * 32;
            cp_async16(&as[row * GPAD + lc4], ag + (size_t)(it * 32) * K);
            cp_async16(&ws[row * GPAD + lc4], wg + (size_t)(it * 32) * K);
        }
    };

    const int NK = K >> 5;

    load_stage(0, 0);
    asm volatile("cp.async.commit_group;\n" ::: "memory");

    for (int kb = 0; kb < NK; kb++) {
        if (kb + 1 < NK) load_stage((kb + 1) & 1, kb + 1);
        asm volatile("cp.async.commit_group;\n" ::: "memory");
        asm volatile("cp.async.wait_group 1;\n" ::: "memory");
        __syncthreads();

        const float* as = AsBuf + (kb & 1) * GEMM_STAGE;
        const float* ws = WsBuf + (kb & 1) * GEMM_STAGE;

#pragma unroll
        for (int ks = 0; ks < 4; ks++) {
            const int kk = ks * 8;
            unsigned a[4][4], b[4][2];
#pragma unroll
            for (int mt = 0; mt < 4; mt++) {
                int r = wm * 64 + mt * 16 + g;
                a[mt][0] = f2tf32(as[r * GPAD + kk + t4]);
                a[mt][1] = f2tf32(as[(r + 8) * GPAD + kk + t4]);
                a[mt][2] = f2tf32(as[r * GPAD + kk + t4 + 4]);
                a[mt][3] = f2tf32(as[(r + 8) * GPAD + kk + t4 + 4]);
            }
#pragma unroll
            for (int nt = 0; nt < 4; nt++) {
                int c = wn * 32 + nt * 8 + g;
                b[nt][0] = f2tf32(ws[c * GPAD + kk + t4]);
                b[nt][1] = f2tf32(ws[c * GPAD + kk + t4 + 4]);
            }
#pragma unroll
            for (int mt = 0; mt < 4; mt++)
#pragma unroll
                for (int nt = 0; nt < 4; nt++)
                    mma_tf32(acc[mt][nt], a[mt], b[nt]);
        }
        __syncthreads();
    }

    // Epilogue: bias (+ReLU) and store
#pragma unroll
    for (int mt = 0; mt < 4; mt++) {
        int row0 = m0 + wm * 64 + mt * 16 + g;
#pragma unroll
        for (int nt = 0; nt < 4; nt++) {
            int col = n0 + wn * 32 + nt * 8 + 2 * t4;
            float b0 = bias[col], b1 = bias[col + 1];
            float v0 = acc[mt][nt][0] + b0;
            float v1 = acc[mt][nt][1] + b1;
            float v2 = acc[mt][nt][2] + b0;
            float v3 = acc[mt][nt][3] + b1;
            if (RELU) {
                v0 = fmaxf(v0, 0.0f); v1 = fmaxf(v1, 0.0f);
                v2 = fmaxf(v2, 0.0f); v3 = fmaxf(v3, 0.0f);
            }
            *reinterpret_cast<float2*>(&C[(size_t)row0 * N + col]) = make_float2(v0, v1);
            *reinterpret_cast<float2*>(&C[(size_t)(row0 + 8) * N + col]) = make_float2(v2, v3);
        }
    }
}

// ---------------------------------------------------------------------------
// Flash attention, TF32 tensor cores.
// Q,K,V,O are [rows, E] with row = token*B + b, channel = h*HD + d.
// grid = (L/128, H, B), block = 256 threads (8 warps).
// Each block: 128 queries; streams 64-key tiles with online softmax.
// Warp w owns query rows [16w, 16w+16).
// ---------------------------------------------------------------------------
#define APAD 68
#define FLASH_SMEM ((128 + 64 + 64 + 128) * APAD * 4)   // 104448 B

__global__ __launch_bounds__(256, 2) void flash_attn_tc_kernel(
    const float* __restrict__ Q, const float* __restrict__ K,
    const float* __restrict__ V, float* __restrict__ O,
    int causal)
{
    extern __shared__ unsigned smu[];
    unsigned* Qs = smu;                       // 128 x APAD
    unsigned* Ks = smu + 128 * APAD;          // 64 x APAD
    unsigned* Vs = smu + (128 + 64) * APAD;   // 64 x APAD
    unsigned* Ps = smu + (128 + 128) * APAD;  // 128 x APAD

    const int tid = threadIdx.x;
    const int lane = tid & 31;
    const int wid = tid >> 5;
    const int g = lane >> 2;
    const int t4 = lane & 3;
    const int qr = wid * 16;       // warp's query-row base within tile

    const int qb = blockIdx.x;
    const int h = blockIdx.y;
    const int b = blockIdx.z;
    const float scale = 0.125f;    // 1/sqrt(64)

    // Load Q tile [128 x 64], pre-scaled, tf32
#pragma unroll
    for (int it = 0; it < 8; it++) {
        int f = tid + it * 256;
        int row = f >> 4;
        int c4 = (f & 15) * 4;
        float4 v = *reinterpret_cast<const float4*>(
            &Q[((size_t)(qb * 128 + row) * BB + b) * EE + h * HD + c4]);
        uint4 u = make_uint4(f2tf32(v.x * scale), f2tf32(v.y * scale),
                             f2tf32(v.z * scale), f2tf32(v.w * scale));
        *reinterpret_cast<uint4*>(&Qs[row * APAD + c4]) = u;
    }

    float o[8][4];
#pragma unroll
    for (int nt = 0; nt < 8; nt++)
#pragma unroll
        for (int r = 0; r < 4; r++) o[nt][r] = 0.0f;
    float m0_ = -1e30f, m1_ = -1e30f, l0_ = 0.0f, l1_ = 0.0f;

    const int nkt = causal ? (2 * qb + 2) : (SK / 64);

    for (int kt = 0; kt < nkt; kt++) {
        __syncthreads();  // prior S/PV reads of Ks/Vs done; Qs published (iter 0)
#pragma unroll
        for (int it = 0; it < 4; it++) {
            int f = tid + it * 256;
            int row = f >> 4;
            int c4 = (f & 15) * 4;
            size_t base = ((size_t)(kt * 64 + row) * BB + b) * EE + h * HD + c4;
            float4 kv = *reinterpret_cast<const float4*>(&K[base]);
            *reinterpret_cast<uint4*>(&Ks[row * APAD + c4]) =
                make_uint4(f2tf32(kv.x), f2tf32(kv.y), f2tf32(kv.z), f2tf32(kv.w));
            float4 vv = *reinterpret_cast<const float4*>(&V[base]);
            *reinterpret_cast<uint4*>(&Vs[row * APAD + c4]) =
                make_uint4(f2tf32(vv.x), f2tf32(vv.y), f2tf32(vv.z), f2tf32(vv.w));
        }
        __syncthreads();

        // S = Q K^T  (warp: m16 x n64, k=64)
        float s[8][4];
#pragma unroll
        for (int nt = 0; nt < 8; nt++)
#pragma unroll
            for (int r = 0; r < 4; r++) s[nt][r] = 0.0f;

#pragma unroll
        for (int ks = 0; ks < 8; ks++) {
            const int kk = ks * 8;
            unsigned a[4];
            a[0] = Qs[(qr + g) * APAD + kk + t4];
            a[1] = Qs[(qr + g + 8) * APAD + kk + t4];
            a[2] = Qs[(qr + g) * APAD + kk + t4 + 4];
            a[3] = Qs[(qr + g + 8) * APAD + kk + t4 + 4];
#pragma unroll
            for (int nt = 0; nt < 8; nt++) {
                unsigned bfr[2];
                bfr[0] = Ks[(nt * 8 + g) * APAD + kk + t4];
                bfr[1] = Ks[(nt * 8 + g) * APAD + kk + t4 + 4];
                mma_tf32(s[nt], a, bfr);
            }
        }

        // Causal mask: only tiles overlapping the diagonal need masking
        if (causal && kt >= 2 * qb) {
            int row0 = qb * 128 + qr + g;
            int row1 = row0 + 8;
#pragma unroll
            for (int nt = 0; nt < 8; nt++) {
                int col = kt * 64 + nt * 8 + 2 * t4;
                if (col > row0)     s[nt][0] = -1e30f;
                if (col + 1 > row0) s[nt][1] = -1e30f;
                if (col > row1)     s[nt][2] = -1e30f;
                if (col + 1 > row1) s[nt][3] = -1e30f;
            }
        }

        // Online softmax (thread owns rows g and g+8 of the warp's m16)
        float mx0 = -1e30f, mx1 = -1e30f;
#pragma unroll
        for (int nt = 0; nt < 8; nt++) {
            mx0 = fmaxf(mx0, fmaxf(s[nt][0], s[nt][1]));
            mx1 = fmaxf(mx1, fmaxf(s[nt][2], s[nt][3]));
        }
        mx0 = fmaxf(mx0, __shfl_xor_sync(0xffffffffu, mx0, 1));
        mx0 = fmaxf(mx0, __shfl_xor_sync(0xffffffffu, mx0, 2));
        mx1 = fmaxf(mx1, __shfl_xor_sync(0xffffffffu, mx1, 1));
        mx1 = fmaxf(mx1, __shfl_xor_sync(0xffffffffu, mx1, 2));

        float nm0 = fmaxf(m0_, mx0);
        float nm1 = fmaxf(m1_, mx1);
        float corr0 = __expf(m0_ - nm0);
        float corr1 = __expf(m1_ - nm1);
        m0_ = nm0; m1_ = nm1;

        float sum0 = 0.0f, sum1 = 0.0f;
#pragma unroll
        for (int nt = 0; nt < 8; nt++) {
            s[nt][0] = __expf(s[nt][0] - nm0);
            s[nt][1] = __expf(s[nt][1] - nm0);
            s[nt][2] = __expf(s[nt][2] - nm1);
            s[nt][3] = __expf(s[nt][3] - nm1);
            sum0 += s[nt][0] + s[nt][1];
            sum1 += s[nt][2] + s[nt][3];
        }
        sum0 += __shfl_xor_sync(0xffffffffu, sum0, 1);
        sum0 += __shfl_xor_sync(0xffffffffu, sum0, 2);
        sum1 += __shfl_xor_sync(0xffffffffu, sum1, 1);
        sum1 += __shfl_xor_sync(0xffffffffu, sum1, 2);
        l0_ = l0_ * corr0 + sum0;
        l1_ = l1_ * corr1 + sum1;
#pragma unroll
        for (int nt = 0; nt < 8; nt++) {
            o[nt][0] *= corr0; o[nt][1] *= corr0;
            o[nt][2] *= corr1; o[nt][3] *= corr1;
        }

        // Store P (tf32) to smem; warp-private rows -> __syncwarp suffices
#pragma unroll
        for (int nt = 0; nt < 8; nt++) {
            *reinterpret_cast<uint2*>(&Ps[(qr + g) * APAD + nt * 8 + 2 * t4]) =
                make_uint2(f2tf32(s[nt][0]), f2tf32(s[nt][1]));
            *reinterpret_cast<uint2*>(&Ps[(qr + g + 8) * APAD + nt * 8 + 2 * t4]) =
                make_uint2(f2tf32(s[nt][2]), f2tf32(s[nt][3]));
        }
        __syncwarp();

        // O += P @ V   (warp: m16 x n64, k = 64 keys)
#pragma unroll
        for (int ks = 0; ks < 8; ks++) {
            const int kk = ks * 8;
            unsigned a[4];
            a[0] = Ps[(qr + g) * APAD + kk + t4];
            a[1] = Ps[(qr + g + 8) * APAD + kk + t4];
            a[2] = Ps[(qr + g) * APAD + kk + t4 + 4];
            a[3] = Ps[(qr + g + 8) * APAD + kk + t4 + 4];
#pragma unroll
            for (int nt = 0; nt < 8; nt++) {
                unsigned bfr[2];
                bfr[0] = Vs[(kk + t4) * APAD + nt * 8 + g];
                bfr[1] = Vs[(kk + t4 + 4) * APAD + nt * 8 + g];
                mma_tf32(o[nt], a, bfr);
            }
        }
    }

    // Normalize + store
    float inv0 = 1.0f / l0_;
    float inv1 = 1.0f / l1_;
    int tok0 = qb * 128 + qr + g;
#pragma unroll
    for (int nt = 0; nt < 8; nt++) {
        int col = h * HD + nt * 8 + 2 * t4;
        *reinterpret_cast<float2*>(&O[((size_t)tok0 * BB + b) * EE + col]) =
            make_float2(o[nt][0] * inv0, o[nt][1] * inv0);
        *reinterpret_cast<float2*>(&O[((size_t)(tok0 + 8) * BB + b) * EE + col]) =
            make_float2(o[nt][2] * inv1, o[nt][3] * inv1);
    }
}

// ---------------------------------------------------------------------------
// Fused add + LayerNorm: out = LN(x + y) * g + b   (row length = 1024)
// ---------------------------------------------------------------------------
__global__ __launch_bounds__(256) void add_ln_kernel(
    const float* __restrict__ X, const float* __restrict__ Y,
    const float* __restrict__ gamma, const float* __restrict__ beta,
    float* __restrict__ out)
{
    const int row = blockIdx.x;
    const int tid = threadIdx.x;
    const size_t base = (size_t)row * EE + tid * 4;

    float4 xv = *reinterpret_cast<const float4*>(&X[base]);
    float4 yv = *reinterpret_cast<const float4*>(&Y[base]);
    float v0 = xv.x + yv.x, v1 = xv.y + yv.y, v2 = xv.z + yv.z, v3 = xv.w + yv.w;

    float s1 = v0 + v1 + v2 + v3;
    float s2 = v0 * v0 + v1 * v1 + v2 * v2 + v3 * v3;

    __shared__ float sm1[8], sm2[8];
#pragma unroll
    for (int off = 16; off > 0; off >>= 1) {
        s1 += __shfl_xor_sync(0xffffffffu, s1, off);
        s2 += __shfl_xor_sync(0xffffffffu, s2, off);
    }
    int wid = tid >> 5, lid = tid & 31;
    if (lid == 0) { sm1[wid] = s1; sm2[wid] = s2; }
    __syncthreads();
    if (wid == 0) {
        s1 = (lid < 8) ? sm1[lid] : 0.0f;
        s2 = (lid < 8) ? sm2[lid] : 0.0f;
#pragma unroll
        for (int off = 4; off > 0; off >>= 1) {
            s1 += __shfl_xor_sync(0xffffffffu, s1, off);
            s2 += __shfl_xor_sync(0xffffffffu, s2, off);
        }
        if (lid == 0) { sm1[0] = s1; sm2[0] = s2; }
    }
    __syncthreads();
    float mean = sm1[0] * (1.0f / EE);
    float var = sm2[0] * (1.0f / EE) - mean * mean;
    float r = rsqrtf(var + 1e-5f);

    int c = tid * 4;
    float4 gv = *reinterpret_cast<const float4*>(&gamma[c]);
    float4 bv = *reinterpret_cast<const float4*>(&beta[c]);
    float4 ov;
    ov.x = (v0 - mean) * r * gv.x + bv.x;
    ov.y = (v1 - mean) * r * gv.y + bv.y;
    ov.z = (v2 - mean) * r * gv.z + bv.z;
    ov.w = (v3 - mean) * r * gv.w + bv.w;
    *reinterpret_cast<float4*>(&out[base]) = ov;
}

// ---------------------------------------------------------------------------
// Host orchestration
// ---------------------------------------------------------------------------
static void launch_gemm(const float* A, const float* W, const float* bias,
                        float* C, int M, int N, int K, bool relu)
{
    dim3 grid(N / 128, M / 128);
    if (relu)
        gemm_tf32_kernel<true><<<grid, 256, GEMM_SMEM>>>(A, W, bias, C, M, N, K);
    else
        gemm_tf32_kernel<false><<<grid, 256, GEMM_SMEM>>>(A, W, bias, C, M, N, K);
}

extern "C" void kernel_launch(void* const* d_in, const int* in_sizes, int n_in,
                              void* d_out, int out_size)
{
    const float* tgt    = (const float*)d_in[0];
    const float* memory = (const float*)d_in[1];
    // d_in[2] = tgt_mask (causal; implemented directly)
    const float* sa_Wq = (const float*)d_in[3];
    const float* sa_bq = (const float*)d_in[4];
    const float* sa_Wk = (const float*)d_in[5];
    const float* sa_bk = (const float*)d_in[6];
    const float* sa_Wv = (const float*)d_in[7];
    const float* sa_bv = (const float*)d_in[8];
    const float* sa_Wo = (const float*)d_in[9];
    const float* sa_bo = (const float*)d_in[10];
    const float* ca_Wq = (const float*)d_in[11];
    const float* ca_bq = (const float*)d_in[12];
    const float* ca_Wk = (const float*)d_in[13];
    const float* ca_bk = (const float*)d_in[14];
    const float* ca_Wv = (const float*)d_in[15];
    const float* ca_bv = (const float*)d_in[16];
    const float* ca_Wo = (const float*)d_in[17];
    const float* ca_bo = (const float*)d_in[18];
    const float* W1    = (const float*)d_in[19];
    const float* b1    = (const float*)d_in[20];
    const float* W2    = (const float*)d_in[21];
    const float* b2    = (const float*)d_in[22];
    const float* ln1_g = (const float*)d_in[23];
    const float* ln1_b = (const float*)d_in[24];
    const float* ln2_g = (const float*)d_in[25];
    const float* ln2_b = (const float*)d_in[26];
    const float* ln3_g = (const float*)d_in[27];
    const float* ln3_b = (const float*)d_in[28];
    float* out = (float*)d_out;

    float *pQ, *pK, *pV, *pA, *pO, *pX1, *pX2, *pH;
    cudaGetSymbolAddress((void**)&pQ, g_Q);
    cudaGetSymbolAddress((void**)&pK, g_K);
    cudaGetSymbolAddress((void**)&pV, g_V);
    cudaGetSymbolAddress((void**)&pA, g_A);
    cudaGetSymbolAddress((void**)&pO, g_O);
    cudaGetSymbolAddress((void**)&pX1, g_X1);
    cudaGetSymbolAddress((void**)&pX2, g_X2);
    cudaGetSymbolAddress((void**)&pH, g_H);

    cudaFuncSetAttribute(gemm_tf32_kernel<false>,
                         cudaFuncAttributeMaxDynamicSharedMemorySize, GEMM_SMEM);
    cudaFuncSetAttribute(gemm_tf32_kernel<true>,
                         cudaFuncAttributeMaxDynamicSharedMemorySize, GEMM_SMEM);
    cudaFuncSetAttribute(flash_attn_tc_kernel,
                         cudaFuncAttributeMaxDynamicSharedMemorySize, FLASH_SMEM);

    dim3 attn_grid(LQ / 128, HH, BB);

    // ---- Self-attention block ----
    launch_gemm(tgt, sa_Wq, sa_bq, pQ, MM, EE, EE, false);
    launch_gemm(tgt, sa_Wk, sa_bk, pK, MM, EE, EE, false);
    launch_gemm(tgt, sa_Wv, sa_bv, pV, MM, EE, EE, false);
    flash_attn_tc_kernel<<<attn_grid, 256, FLASH_SMEM>>>(pQ, pK, pV, pA, 1);
    launch_gemm(pA, sa_Wo, sa_bo, pO, MM, EE, EE, false);
    add_ln_kernel<<<MM, 256>>>(tgt, pO, ln1_g, ln1_b, pX1);

    // ---- Cross-attention block ----
    launch_gemm(pX1, ca_Wq, ca_bq, pQ, MM, EE, EE, false);
    launch_gemm(memory, ca_Wk, ca_bk, pK, MM, EE, EE, false);
    launch_gemm(memory, ca_Wv, ca_bv, pV, MM, EE, EE, false);
    flash_attn_tc_kernel<<<attn_grid, 256, FLASH_SMEM>>>(pQ, pK, pV, pA, 0);
    launch_gemm(pA, ca_Wo, ca_bo, pO, MM, EE, EE, false);
    add_ln_kernel<<<MM, 256>>>(pX1, pO, ln2_g, ln2_b, pX2);

    // ---- FFN block ----
    launch_gemm(pX2, W1, b1, pH, MM, FF, EE, true);   // ReLU fused
    launch_gemm(pH, W2, b2, pO, MM, EE, FF, false);
    add_ln_kernel<<<MM, 256>>>(pX2, pO, ln3_g, ln3_b, out);
}

// round 6
// speedup vs baseline: 3.9328x; 1.1152x over previous
#include <cuda_runtime.h>
#include <cuda_bf16.h>
#include <cstdint>

// Problem constants
#define LQ 2048
#define SK 2048
#define BB 4
#define EE 1024
#define HH 16
#define HD 64
#define FF 4096
#define MM (LQ * BB)   // 8192 rows

// ---------------------------------------------------------------------------
// Scratch buffers (__device__ globals: allocation-free per harness rules)
// ---------------------------------------------------------------------------
__device__ float g_Q[MM * EE];
__device__ float g_K[MM * EE];
__device__ float g_V[MM * EE];
__device__ float g_A[MM * EE];
__device__ float g_O[MM * EE];
__device__ float g_X1[MM * EE];
__device__ float g_X2[MM * EE];
__device__ float g_H[MM * FF];

// ---------------------------------------------------------------------------
// Helpers
// ---------------------------------------------------------------------------
__device__ __forceinline__ void mma_tf32(float* c, const unsigned* a, const unsigned* b) {
    asm volatile(
        "mma.sync.aligned.m16n8k8.row.col.f32.tf32.tf32.f32 "
        "{%0,%1,%2,%3}, {%4,%5,%6,%7}, {%8,%9}, {%0,%1,%2,%3};\n"
        : "+f"(c[0]), "+f"(c[1]), "+f"(c[2]), "+f"(c[3])
        : "r"(a[0]), "r"(a[1]), "r"(a[2]), "r"(a[3]), "r"(b[0]), "r"(b[1]));
}

__device__ __forceinline__ void cp_async16(void* dst, const void* src) {
    unsigned d = (unsigned)__cvta_generic_to_shared(dst);
    asm volatile("cp.async.cg.shared.global [%0], [%1], 16;\n" :: "r"(d), "l"(src));
}

// ---------------------------------------------------------------------------
// TF32 tensor-core GEMM (mma.sync), raw-fp32 operands (HW rz truncation),
// paired-k LDS.64 fragment loads.
// C[M,N] = A[M,K] @ W[N,K]^T + bias, optional ReLU.
// Block tile 128x128, BK=32, 256 threads = 8 warps (2x4), warp tile 64x32.
// Double-buffered cp.async. Row stride 40 words (pair-stride 20 == 4 mod 16
// -> conflict-free LDS.64 fragment loads).
//
// k-permutation trick: within each k8 instruction, thread t4 supplies
// physical columns (2*t4, 2*t4+1) as logical k (t4, t4+4). Applied to BOTH
// A and B fragments -> dot product unchanged, loads become one LDS.64.
// ---------------------------------------------------------------------------
#define GPAD 40
#define GSTAGE (128 * GPAD)                 // words per tile
#define GEMM_SMEM (4 * GSTAGE * 4)          // 2 stages x (A+W), bytes = 81920

template <bool RELU>
__global__ __launch_bounds__(256, 2) void gemm_tf32_kernel(
    const float* __restrict__ A, const float* __restrict__ W,
    const float* __restrict__ bias, float* __restrict__ C,
    int M, int N, int K)
{
    extern __shared__ float gsm[];
    float* AsBuf = gsm;                     // [2][128*GPAD]
    float* WsBuf = gsm + 2 * GSTAGE;        // [2][128*GPAD]

    const int tid = threadIdx.x;
    const int lane = tid & 31;
    const int wid = tid >> 5;
    const int wm = wid >> 2;        // 0..1
    const int wn = wid & 3;         // 0..3
    const int g = lane >> 2;        // 0..7
    const int t4 = lane & 3;        // 0..3

    const int m0 = blockIdx.y * 128;
    const int n0 = blockIdx.x * 128;

    const int lrow = tid >> 3;           // 0..31
    const int lseg = (tid & 7) * 4;      // word offset 0,4,...,28

    const float* Ag = A + (size_t)(m0 + lrow) * K + lseg;
    const float* Wg = W + (size_t)(n0 + lrow) * K + lseg;

    float acc[4][4][4];
#pragma unroll
    for (int mt = 0; mt < 4; mt++)
#pragma unroll
        for (int nt = 0; nt < 4; nt++)
#pragma unroll
            for (int r = 0; r < 4; r++) acc[mt][nt][r] = 0.0f;

    auto load_stage = [&](int st, int kb) {
        float* as = AsBuf + st * GSTAGE;
        float* ws = WsBuf + st * GSTAGE;
        const float* ag = Ag + kb * 32;
        const float* wg = Wg + kb * 32;
#pragma unroll
        for (int it = 0; it < 4; it++) {
            int row = lrow + it * 32;
            cp_async16(&as[row * GPAD + lseg], ag + (size_t)(it * 32) * K);
            cp_async16(&ws[row * GPAD + lseg], wg + (size_t)(it * 32) * K);
        }
        asm volatile("cp.async.commit_group;\n" ::: "memory");
    };

    const int NK = K >> 5;   // BK = 32

    load_stage(0, 0);

    for (int kb = 0; kb < NK; kb++) {
        if (kb + 1 < NK) {
            load_stage((kb + 1) & 1, kb + 1);
            asm volatile("cp.async.wait_group 1;\n" ::: "memory");
        } else {
            asm volatile("cp.async.wait_group 0;\n" ::: "memory");
        }
        __syncthreads();

        const float* as = AsBuf + (kb & 1) * GSTAGE;
        const float* ws = WsBuf + (kb & 1) * GSTAGE;

#pragma unroll
        for (int ks = 0; ks < 4; ks++) {
            const int kc = ks * 8 + 2 * t4;   // physical column pair base
            unsigned a[4][4], b[4][2];
#pragma unroll
            for (int mt = 0; mt < 4; mt++) {
                int r = wm * 64 + mt * 16 + g;
                uint2 p0 = *reinterpret_cast<const uint2*>(&as[r * GPAD + kc]);
                uint2 p1 = *reinterpret_cast<const uint2*>(&as[(r + 8) * GPAD + kc]);
                a[mt][0] = p0.x; a[mt][1] = p1.x; a[mt][2] = p0.y; a[mt][3] = p1.y;
            }
#pragma unroll
            for (int nt = 0; nt < 4; nt++) {
                int c = wn * 32 + nt * 8 + g;
                uint2 pb = *reinterpret_cast<const uint2*>(&ws[c * GPAD + kc]);
                b[nt][0] = pb.x; b[nt][1] = pb.y;
            }
#pragma unroll
            for (int mt = 0; mt < 4; mt++)
#pragma unroll
                for (int nt = 0; nt < 4; nt++)
                    mma_tf32(acc[mt][nt], a[mt], b[nt]);
        }
        __syncthreads();
    }

    // Epilogue: bias (+ReLU) and store (c layout: rows g,g+8; cols 2t4,2t4+1)
#pragma unroll
    for (int mt = 0; mt < 4; mt++) {
        int row0 = m0 + wm * 64 + mt * 16 + g;
#pragma unroll
        for (int nt = 0; nt < 4; nt++) {
            int col = n0 + wn * 32 + nt * 8 + 2 * t4;
            float b0 = bias[col], b1 = bias[col + 1];
            float v0 = acc[mt][nt][0] + b0;
            float v1 = acc[mt][nt][1] + b1;
            float v2 = acc[mt][nt][2] + b0;
            float v3 = acc[mt][nt][3] + b1;
            if (RELU) {
                v0 = fmaxf(v0, 0.0f); v1 = fmaxf(v1, 0.0f);
                v2 = fmaxf(v2, 0.0f); v3 = fmaxf(v3, 0.0f);
            }
            *reinterpret_cast<float2*>(&C[(size_t)row0 * N + col]) = make_float2(v0, v1);
            *reinterpret_cast<float2*>(&C[(size_t)(row0 + 8) * N + col]) = make_float2(v2, v3);
        }
    }
}

// ---------------------------------------------------------------------------
// Flash attention, TF32 mma.sync, raw-fp32 operands (rz), paired-k loads.
// Q,K,V,O are [rows, E] with row = token*B + b, channel = h*HD + d.
// grid = (L/128, H, B), block = 256 threads (8 warps).
// Warp w owns query rows [16w, 16w+16).
//
// QK: Qs/Ks k-major, paired-k trick (both operands) -> LDS.64.
// PV: standard k-mapping; P stored in natural column order (A operand,
//     scalar loads); V stored TRANSPOSED as VsT[dim][key] with key-slot
//     permutation vperm so that slots (2t4, 2t4+1) hold keys (t4, t4+4):
//     B fragment = one LDS.64. Extra XOR (2*((d>>2)&3)) on the slot index
//     spreads transpose-store banks (2-way instead of 16-way).
// ---------------------------------------------------------------------------
#define APAD 72
#define FLASH_SMEM ((128 + 64 + 64 + 128) * APAD * 4)   // 110592 B

__device__ __forceinline__ int vperm(int key) {   // key in [0,64)
    int blk = key & ~7, u = key & 7;
    return blk + ((u < 4) ? (2 * u) : (2 * (u - 4) + 1));
}

__global__ __launch_bounds__(256, 2) void flash_attn_tc_kernel(
    const float* __restrict__ Q, const float* __restrict__ K,
    const float* __restrict__ V, float* __restrict__ O,
    int causal)
{
    extern __shared__ float smf[];
    float* Qs  = smf;                        // 128 x APAD (q row, dim col)
    float* Ks  = smf + 128 * APAD;           // 64 x APAD  (key row, dim col)
    float* VsT = smf + (128 + 64) * APAD;    // 64 x APAD  (dim row, key col, permuted)
    float* Ps  = smf + (128 + 128) * APAD;   // 128 x APAD (q row, key col)

    const int tid = threadIdx.x;
    const int lane = tid & 31;
    const int wid = tid >> 5;
    const int g = lane >> 2;
    const int t4 = lane & 3;
    const int qr = wid * 16;

    const int qb = blockIdx.x;
    const int h = blockIdx.y;
    const int b = blockIdx.z;
    const float scale = 0.125f;

    // Load Q tile [128 x 64], pre-scaled
#pragma unroll
    for (int it = 0; it < 8; it++) {
        int f = tid + it * 256;
        int row = f >> 4;
        int c4 = (f & 15) * 4;
        float4 v = *reinterpret_cast<const float4*>(
            &Q[((size_t)(qb * 128 + row) * BB + b) * EE + h * HD + c4]);
        *reinterpret_cast<float4*>(&Qs[row * APAD + c4]) =
            make_float4(v.x * scale, v.y * scale, v.z * scale, v.w * scale);
    }

    float o[8][4];
#pragma unroll
    for (int nt = 0; nt < 8; nt++)
#pragma unroll
        for (int r = 0; r < 4; r++) o[nt][r] = 0.0f;
    float m0_ = -1e30f, m1_ = -1e30f, l0_ = 0.0f, l1_ = 0.0f;

    const int nkt = causal ? (2 * qb + 2) : (SK / 64);

    for (int kt = 0; kt < nkt; kt++) {
        __syncthreads();
#pragma unroll
        for (int it = 0; it < 4; it++) {
            int f = tid + it * 256;
            int row = f >> 4;           // local key
            int c4 = (f & 15) * 4;      // dim
            size_t base = ((size_t)(kt * 64 + row) * BB + b) * EE + h * HD + c4;
            // K: direct (key-major)
            *reinterpret_cast<float4*>(&Ks[row * APAD + c4]) =
                *reinterpret_cast<const float4*>(&K[base]);
            // V: transpose into VsT[dim][perm(key) ^ xor2]
            float4 vv = *reinterpret_cast<const float4*>(&V[base]);
            int pc = vperm(row);
#pragma unroll
            for (int j = 0; j < 4; j++) {
                int d = c4 + j;
                int col = pc ^ (2 * ((d >> 2) & 3));
                VsT[d * APAD + col] = (&vv.x)[j];
            }
        }
        __syncthreads();

        // S = Q K^T (paired-k on both operands)
        float s[8][4];
#pragma unroll
        for (int nt = 0; nt < 8; nt++)
#pragma unroll
            for (int r = 0; r < 4; r++) s[nt][r] = 0.0f;

#pragma unroll
        for (int ks = 0; ks < 8; ks++) {
            const int kc = ks * 8 + 2 * t4;
            uint2 q0 = *reinterpret_cast<const uint2*>(&Qs[(qr + g) * APAD + kc]);
            uint2 q1 = *reinterpret_cast<const uint2*>(&Qs[(qr + g + 8) * APAD + kc]);
            unsigned a[4] = {q0.x, q1.x, q0.y, q1.y};
#pragma unroll
            for (int nt = 0; nt < 8; nt++) {
                uint2 kb2 = *reinterpret_cast<const uint2*>(&Ks[(nt * 8 + g) * APAD + kc]);
                unsigned bfr[2] = {kb2.x, kb2.y};
                mma_tf32(s[nt], a, bfr);
            }
        }

        // Causal mask (c cols are 2t4, 2t4+1)
        if (causal && kt >= 2 * qb) {
            int row0 = qb * 128 + qr + g;
            int row1 = row0 + 8;
#pragma unroll
            for (int nt = 0; nt < 8; nt++) {
                int col = kt * 64 + nt * 8 + 2 * t4;
                if (col > row0)     s[nt][0] = -1e30f;
                if (col + 1 > row0) s[nt][1] = -1e30f;
                if (col > row1)     s[nt][2] = -1e30f;
                if (col + 1 > row1) s[nt][3] = -1e30f;
            }
        }

        // Online softmax (rows g and g+8)
        float mx0 = -1e30f, mx1 = -1e30f;
#pragma unroll
        for (int nt = 0; nt < 8; nt++) {
            mx0 = fmaxf(mx0, fmaxf(s[nt][0], s[nt][1]));
            mx1 = fmaxf(mx1, fmaxf(s[nt][2], s[nt][3]));
        }
        mx0 = fmaxf(mx0, __shfl_xor_sync(0xffffffffu, mx0, 1));
        mx0 = fmaxf(mx0, __shfl_xor_sync(0xffffffffu, mx0, 2));
        mx1 = fmaxf(mx1, __shfl_xor_sync(0xffffffffu, mx1, 1));
        mx1 = fmaxf(mx1, __shfl_xor_sync(0xffffffffu, mx1, 2));

        float nm0 = fmaxf(m0_, mx0);
        float nm1 = fmaxf(m1_, mx1);
        float corr0 = __expf(m0_ - nm0);
        float corr1 = __expf(m1_ - nm1);
        m0_ = nm0; m1_ = nm1;

        float sum0 = 0.0f, sum1 = 0.0f;
#pragma unroll
        for (int nt = 0; nt < 8; nt++) {
            s[nt][0] = __expf(s[nt][0] - nm0);
            s[nt][1] = __expf(s[nt][1] - nm0);
            s[nt][2] = __expf(s[nt][2] - nm1);
            s[nt][3] = __expf(s[nt][3] - nm1);
            sum0 += s[nt][0] + s[nt][1];
            sum1 += s[nt][2] + s[nt][3];
        }
        sum0 += __shfl_xor_sync(0xffffffffu, sum0, 1);
        sum0 += __shfl_xor_sync(0xffffffffu, sum0, 2);
        sum1 += __shfl_xor_sync(0xffffffffu, sum1, 1);
        sum1 += __shfl_xor_sync(0xffffffffu, sum1, 2);
        l0_ = l0_ * corr0 + sum0;
        l1_ = l1_ * corr1 + sum1;
#pragma unroll
        for (int nt = 0; nt < 8; nt++) {
            o[nt][0] *= corr0; o[nt][1] *= corr0;
            o[nt][2] *= corr1; o[nt][3] *= corr1;
        }

        // Store P (natural column order; c cols are 2t4,2t4+1 -> float2)
#pragma unroll
        for (int nt = 0; nt < 8; nt++) {
            *reinterpret_cast<float2*>(&Ps[(qr + g) * APAD + nt * 8 + 2 * t4]) =
                make_float2(s[nt][0], s[nt][1]);
            *reinterpret_cast<float2*>(&Ps[(qr + g + 8) * APAD + nt * 8 + 2 * t4]) =
                make_float2(s[nt][2], s[nt][3]);
        }
        __syncwarp();

        // O += P @ V  (A: standard scalar loads; B: LDS.64 from permuted VsT)
#pragma unroll
        for (int ks = 0; ks < 8; ks++) {
            const int kk = ks * 8;
            unsigned a[4];
            a[0] = __float_as_uint(Ps[(qr + g) * APAD + kk + t4]);
            a[1] = __float_as_uint(Ps[(qr + g + 8) * APAD + kk + t4]);
            a[2] = __float_as_uint(Ps[(qr + g) * APAD + kk + t4 + 4]);
            a[3] = __float_as_uint(Ps[(qr + g + 8) * APAD + kk + t4 + 4]);
#pragma unroll
            for (int nt = 0; nt < 8; nt++) {
                int d = nt * 8 + g;
                int col = (kk + 2 * t4) ^ (2 * ((d >> 2) & 3));
                uint2 vb = *reinterpret_cast<const uint2*>(&VsT[d * APAD + col]);
                unsigned bfr[2] = {vb.x, vb.y};
                mma_tf32(o[nt], a, bfr);
            }
        }
    }

    // Normalize + store
    float inv0 = 1.0f / l0_;
    float inv1 = 1.0f / l1_;
    int tok0 = qb * 128 + qr + g;
#pragma unroll
    for (int nt = 0; nt < 8; nt++) {
        int col = h * HD + nt * 8 + 2 * t4;
        *reinterpret_cast<float2*>(&O[((size_t)tok0 * BB + b) * EE + col]) =
            make_float2(o[nt][0] * inv0, o[nt][1] * inv0);
        *reinterpret_cast<float2*>(&O[((size_t)(tok0 + 8) * BB + b) * EE + col]) =
            make_float2(o[nt][2] * inv1, o[nt][3] * inv1);
    }
}

// ---------------------------------------------------------------------------
// Fused add + LayerNorm: out = LN(x + y) * g + b   (row length = 1024)
// ---------------------------------------------------------------------------
__global__ __launch_bounds__(256) void add_ln_kernel(
    const float* __restrict__ X, const float* __restrict__ Y,
    const float* __restrict__ gamma, const float* __restrict__ beta,
    float* __restrict__ out)
{
    const int row = blockIdx.x;
    const int tid = threadIdx.x;
    const size_t base = (size_t)row * EE + tid * 4;

    float4 xv = *reinterpret_cast<const float4*>(&X[base]);
    float4 yv = *reinterpret_cast<const float4*>(&Y[base]);
    float v0 = xv.x + yv.x, v1 = xv.y + yv.y, v2 = xv.z + yv.z, v3 = xv.w + yv.w;

    float s1 = v0 + v1 + v2 + v3;
    float s2 = v0 * v0 + v1 * v1 + v2 * v2 + v3 * v3;

    __shared__ float sm1[8], sm2[8];
#pragma unroll
    for (int off = 16; off > 0; off >>= 1) {
        s1 += __shfl_xor_sync(0xffffffffu, s1, off);
        s2 += __shfl_xor_sync(0xffffffffu, s2, off);
    }
    int wid = tid >> 5, lid = tid & 31;
    if (lid == 0) { sm1[wid] = s1; sm2[wid] = s2; }
    __syncthreads();
    if (wid == 0) {
        s1 = (lid < 8) ? sm1[lid] : 0.0f;
        s2 = (lid < 8) ? sm2[lid] : 0.0f;
#pragma unroll
        for (int off = 4; off > 0; off >>= 1) {
            s1 += __shfl_xor_sync(0xffffffffu, s1, off);
            s2 += __shfl_xor_sync(0xffffffffu, s2, off);
        }
        if (lid == 0) { sm1[0] = s1; sm2[0] = s2; }
    }
    __syncthreads();
    float mean = sm1[0] * (1.0f / EE);
    float var = sm2[0] * (1.0f / EE) - mean * mean;
    float r = rsqrtf(var + 1e-5f);

    int c = tid * 4;
    float4 gv = *reinterpret_cast<const float4*>(&gamma[c]);
    float4 bv = *reinterpret_cast<const float4*>(&beta[c]);
    float4 ov;
    ov.x = (v0 - mean) * r * gv.x + bv.x;
    ov.y = (v1 - mean) * r * gv.y + bv.y;
    ov.z = (v2 - mean) * r * gv.z + bv.z;
    ov.w = (v3 - mean) * r * gv.w + bv.w;
    *reinterpret_cast<float4*>(&out[base]) = ov;
}

// ---------------------------------------------------------------------------
// Host orchestration
// ---------------------------------------------------------------------------
static void launch_gemm(const float* A, const float* W, const float* bias,
                        float* C, int M, int N, int K, bool relu)
{
    dim3 grid(N / 128, M / 128);
    if (relu)
        gemm_tf32_kernel<true><<<grid, 256, GEMM_SMEM>>>(A, W, bias, C, M, N, K);
    else
        gemm_tf32_kernel<false><<<grid, 256, GEMM_SMEM>>>(A, W, bias, C, M, N, K);
}

extern "C" void kernel_launch(void* const* d_in, const int* in_sizes, int n_in,
                              void* d_out, int out_size)
{
    const float* tgt    = (const float*)d_in[0];
    const float* memory = (const float*)d_in[1];
    // d_in[2] = tgt_mask (causal; implemented directly)
    const float* sa_Wq = (const float*)d_in[3];
    const float* sa_bq = (const float*)d_in[4];
    const float* sa_Wk = (const float*)d_in[5];
    const float* sa_bk = (const float*)d_in[6];
    const float* sa_Wv = (const float*)d_in[7];
    const float* sa_bv = (const float*)d_in[8];
    const float* sa_Wo = (const float*)d_in[9];
    const float* sa_bo = (const float*)d_in[10];
    const float* ca_Wq = (const float*)d_in[11];
    const float* ca_bq = (const float*)d_in[12];
    const float* ca_Wk = (const float*)d_in[13];
    const float* ca_bk = (const float*)d_in[14];
    const float* ca_Wv = (const float*)d_in[15];
    const float* ca_bv = (const float*)d_in[16];
    const float* ca_Wo = (const float*)d_in[17];
    const float* ca_bo = (const float*)d_in[18];
    const float* W1    = (const float*)d_in[19];
    const float* b1    = (const float*)d_in[20];
    const float* W2    = (const float*)d_in[21];
    const float* b2    = (const float*)d_in[22];
    const float* ln1_g = (const float*)d_in[23];
    const float* ln1_b = (const float*)d_in[24];
    const float* ln2_g = (const float*)d_in[25];
    const float* ln2_b = (const float*)d_in[26];
    const float* ln3_g = (const float*)d_in[27];
    const float* ln3_b = (const float*)d_in[28];
    float* out = (float*)d_out;

    float *pQ, *pK, *pV, *pA, *pO, *pX1, *pX2, *pH;
    cudaGetSymbolAddress((void**)&pQ, g_Q);
    cudaGetSymbolAddress((void**)&pK, g_K);
    cudaGetSymbolAddress((void**)&pV, g_V);
    cudaGetSymbolAddress((void**)&pA, g_A);
    cudaGetSymbolAddress((void**)&pO, g_O);
    cudaGetSymbolAddress((void**)&pX1, g_X1);
    cudaGetSymbolAddress((void**)&pX2, g_X2);
    cudaGetSymbolAddress((void**)&pH, g_H);

    cudaFuncSetAttribute(gemm_tf32_kernel<false>,
                         cudaFuncAttributeMaxDynamicSharedMemorySize, GEMM_SMEM);
    cudaFuncSetAttribute(gemm_tf32_kernel<true>,
                         cudaFuncAttributeMaxDynamicSharedMemorySize, GEMM_SMEM);
    cudaFuncSetAttribute(flash_attn_tc_kernel,
                         cudaFuncAttributeMaxDynamicSharedMemorySize, FLASH_SMEM);

    dim3 attn_grid(LQ / 128, HH, BB);

    // ---- Self-attention block ----
    launch_gemm(tgt, sa_Wq, sa_bq, pQ, MM, EE, EE, false);
    launch_gemm(tgt, sa_Wk, sa_bk, pK, MM, EE, EE, false);
    launch_gemm(tgt, sa_Wv, sa_bv, pV, MM, EE, EE, false);
    flash_attn_tc_kernel<<<attn_grid, 256, FLASH_SMEM>>>(pQ, pK, pV, pA, 1);
    launch_gemm(pA, sa_Wo, sa_bo, pO, MM, EE, EE, false);
    add_ln_kernel<<<MM, 256>>>(tgt, pO, ln1_g, ln1_b, pX1);

    // ---- Cross-attention block ----
    launch_gemm(pX1, ca_Wq, ca_bq, pQ, MM, EE, EE, false);
    launch_gemm(memory, ca_Wk, ca_bk, pK, MM, EE, EE, false);
    launch_gemm(memory, ca_Wv, ca_bv, pV, MM, EE, EE, false);
    flash_attn_tc_kernel<<<attn_grid, 256, FLASH_SMEM>>>(pQ, pK, pV, pA, 0);
    launch_gemm(pA, ca_Wo, ca_bo, pO, MM, EE, EE, false);
    add_ln_kernel<<<MM, 256>>>(pX1, pO, ln2_g, ln2_b, pX2);

    // ---- FFN block ----
    launch_gemm(pX2, W1, b1, pH, MM, FF, EE, true);   // ReLU fused
    launch_gemm(pH, W2, b2, pO, MM, EE, FF, false);
    add_ln_kernel<<<MM, 256>>>(pX2, pO, ln3_g, ln3_b, out);
}

// round 8
// speedup vs baseline: 7.9193x; 2.0137x over previous
#include <cuda_runtime.h>
#include <cuda_fp16.h>
#include <cstdint>

// Problem constants
#define LQ 2048
#define SK 2048
#define BB 4
#define EE 1024
#define HH 16
#define HD 64
#define FF 4096
#define MM (LQ * BB)   // 8192 rows

// ---------------------------------------------------------------------------
// Scratch buffers (__device__ globals: allocation-free per harness rules)
// ---------------------------------------------------------------------------
__device__ __half hW_saq[EE * EE], hW_sak[EE * EE], hW_sav[EE * EE], hW_sao[EE * EE];
__device__ __half hW_caq[EE * EE], hW_cak[EE * EE], hW_cav[EE * EE], hW_cao[EE * EE];
__device__ __half hW1[FF * EE], hW2[EE * FF];
__device__ __half h_tgt[MM * EE], h_mem[MM * EE];
__device__ __half h_Q[MM * EE], h_K[MM * EE], h_V[MM * EE], h_A[MM * EE];
__device__ __half h_X[MM * EE];
__device__ __half h_H[MM * FF];
__device__ float f_O[MM * EE], f_X1[MM * EE], f_X2[MM * EE];

// ---------------------------------------------------------------------------
// Helpers
// ---------------------------------------------------------------------------
__device__ __forceinline__ uint32_t smem_u32(const void* p) {
    uint32_t a;
    asm("{ .reg .u64 t; cvta.to.shared.u64 t, %1; cvt.u32.u64 %0, t; }"
        : "=r"(a) : "l"(p));
    return a;
}

__device__ __forceinline__ void mma_f16(float* c, const unsigned* a, const unsigned* b) {
    asm volatile(
        "mma.sync.aligned.m16n8k16.row.col.f32.f16.f16.f32 "
        "{%0,%1,%2,%3}, {%4,%5,%6,%7}, {%8,%9}, {%0,%1,%2,%3};\n"
        : "+f"(c[0]), "+f"(c[1]), "+f"(c[2]), "+f"(c[3])
        : "r"(a[0]), "r"(a[1]), "r"(a[2]), "r"(a[3]), "r"(b[0]), "r"(b[1]));
}

__device__ __forceinline__ void ldsm_x4(unsigned* r, uint32_t addr) {
    asm volatile("ldmatrix.sync.aligned.m8n8.x4.shared.b16 {%0,%1,%2,%3}, [%4];\n"
        : "=r"(r[0]), "=r"(r[1]), "=r"(r[2]), "=r"(r[3]) : "r"(addr));
}
__device__ __forceinline__ void ldsm_x2(unsigned* r, uint32_t addr) {
    asm volatile("ldmatrix.sync.aligned.m8n8.x2.shared.b16 {%0,%1}, [%2];\n"
        : "=r"(r[0]), "=r"(r[1]) : "r"(addr));
}
__device__ __forceinline__ void ldsm_x2t(unsigned* r, uint32_t addr) {
    asm volatile("ldmatrix.sync.aligned.m8n8.x2.trans.shared.b16 {%0,%1}, [%2];\n"
        : "=r"(r[0]), "=r"(r[1]) : "r"(addr));
}

__device__ __forceinline__ void cp_async16s(uint32_t daddr, const void* src) {
    asm volatile("cp.async.cg.shared.global [%0], [%1], 16;\n" :: "r"(daddr), "l"(src));
}

// ---------------------------------------------------------------------------
// fp32 -> fp16 convert (rne)
// ---------------------------------------------------------------------------
__global__ __launch_bounds__(256) void f2h_kernel(
    const float* __restrict__ in, __half* __restrict__ out, int n)
{
    int i = (blockIdx.x * 256 + threadIdx.x) * 4;
    if (i < n) {
        float4 v = *reinterpret_cast<const float4*>(in + i);
        __half2 h0 = __floats2half2_rn(v.x, v.y);
        __half2 h1 = __floats2half2_rn(v.z, v.w);
        *reinterpret_cast<__half2*>(out + i) = h0;
        *reinterpret_cast<__half2*>(out + i + 2) = h1;
    }
}

// ---------------------------------------------------------------------------
// FP16 tensor-core GEMM (mma.sync m16n8k16), fp32 accumulate.
// C[M,N] = A[M,K] @ W[N,K]^T + bias, optional ReLU, OutT in {float, __half}.
// Block tile 128x128, BK=64 halves, 256 threads = 8 warps (2x4),
// warp tile 64x32. 3-stage cp.async pipeline. Smem rows: 128B data,
// XOR-swizzled 16B chunks (chunk ^= row&7) -> conflict-free ldmatrix + STS.
// ---------------------------------------------------------------------------
#define GEMM_TILE_B (128 * 128)                 // bytes per operand tile
#define GEMM_STAGE_B (2 * GEMM_TILE_B)          // A + W
#define GEMM_SMEM (3 * GEMM_STAGE_B)            // 98304 B

template <typename OutT, bool RELU>
__global__ __launch_bounds__(256, 2) void gemm_f16_kernel(
    const __half* __restrict__ A, const __half* __restrict__ W,
    const float* __restrict__ bias, OutT* __restrict__ C,
    int M, int N, int K)
{
    extern __shared__ char gsm[];
    const uint32_t sb = smem_u32(gsm);

    const int tid = threadIdx.x;
    const int lane = tid & 31;
    const int wid = tid >> 5;
    const int wm = wid >> 2, wn = wid & 3;
    const int g = lane >> 2, t4 = lane & 3;
    const int r8 = lane & 7, hi8 = (lane >> 3) & 1, hi16 = lane >> 4;

    const int m0 = blockIdx.y * 128;
    const int n0 = blockIdx.x * 128;

    // Fragment address bases (per stage add stage offset)
    int rowOffA[4], rowOffB[4];
#pragma unroll
    for (int mt = 0; mt < 4; mt++)
        rowOffA[mt] = (wm * 64 + mt * 16 + r8 + 8 * hi8) * 128;
#pragma unroll
    for (int nt = 0; nt < 4; nt++)
        rowOffB[nt] = (wn * 32 + nt * 8 + r8) * 128;

    float acc[4][4][4];
#pragma unroll
    for (int mt = 0; mt < 4; mt++)
#pragma unroll
        for (int nt = 0; nt < 4; nt++)
#pragma unroll
            for (int r = 0; r < 4; r++) acc[mt][nt][r] = 0.0f;

    const int lrow = tid >> 3;      // 0..31
    const int lseg = tid & 7;       // 0..7 (16B chunk)

    auto load_stage = [&](int st, int kb) {
        uint32_t abase = sb + st * GEMM_STAGE_B;
        uint32_t wbase = abase + GEMM_TILE_B;
        const __half* ag = A + (size_t)(m0 + lrow) * K + kb * 64 + lseg * 8;
        const __half* wg = W + (size_t)(n0 + lrow) * K + kb * 64 + lseg * 8;
#pragma unroll
        for (int it = 0; it < 4; it++) {
            int row = lrow + it * 32;
            uint32_t doff = row * 128 + ((lseg ^ (row & 7)) << 4);
            cp_async16s(abase + doff, ag + (size_t)(it * 32) * K);
            cp_async16s(wbase + doff, wg + (size_t)(it * 32) * K);
        }
        asm volatile("cp.async.commit_group;\n" ::: "memory");
    };

    const int NK = K >> 6;   // BK = 64 halves

    load_stage(0, 0);
    load_stage(1, 1);
    load_stage(2, 2);

    for (int kb = 0; kb < NK; kb++) {
        if (kb < NK - 2)       asm volatile("cp.async.wait_group 2;\n" ::: "memory");
        else if (kb == NK - 2) asm volatile("cp.async.wait_group 1;\n" ::: "memory");
        else                   asm volatile("cp.async.wait_group 0;\n" ::: "memory");
        __syncthreads();

        const uint32_t sa = sb + (kb % 3) * GEMM_STAGE_B;
        const uint32_t sw = sa + GEMM_TILE_B;

#pragma unroll
        for (int ks = 0; ks < 4; ks++) {
            unsigned a[4][4], bf[4][2];
            const int cA = ks * 2 + hi16;
            const int cB = ks * 2 + hi8;
#pragma unroll
            for (int mt = 0; mt < 4; mt++)
                ldsm_x4(a[mt], sa + rowOffA[mt] + ((cA ^ r8) << 4));
#pragma unroll
            for (int nt = 0; nt < 4; nt++)
                ldsm_x2(bf[nt], sw + rowOffB[nt] + ((cB ^ r8) << 4));
#pragma unroll
            for (int mt = 0; mt < 4; mt++)
#pragma unroll
                for (int nt = 0; nt < 4; nt++)
                    mma_f16(acc[mt][nt], a[mt], bf[nt]);
        }

        if (kb + 3 < NK) {
            __syncthreads();   // all warps done reading stage kb%3
            load_stage(kb % 3, kb + 3);
        }
    }

    // Epilogue
#pragma unroll
    for (int mt = 0; mt < 4; mt++) {
        int row0 = m0 + wm * 64 + mt * 16 + g;
#pragma unroll
        for (int nt = 0; nt < 4; nt++) {
            int col = n0 + wn * 32 + nt * 8 + 2 * t4;
            float b0 = bias[col], b1 = bias[col + 1];
            float v0 = acc[mt][nt][0] + b0;
            float v1 = acc[mt][nt][1] + b1;
            float v2 = acc[mt][nt][2] + b0;
            float v3 = acc[mt][nt][3] + b1;
            if (RELU) {
                v0 = fmaxf(v0, 0.0f); v1 = fmaxf(v1, 0.0f);
                v2 = fmaxf(v2, 0.0f); v3 = fmaxf(v3, 0.0f);
            }
            if (sizeof(OutT) == 2) {
                __half2* p0 = reinterpret_cast<__half2*>((__half*)C + (size_t)row0 * N + col);
                __half2* p1 = reinterpret_cast<__half2*>((__half*)C + (size_t)(row0 + 8) * N + col);
                *p0 = __floats2half2_rn(v0, v1);
                *p1 = __floats2half2_rn(v2, v3);
            } else {
                *reinterpret_cast<float2*>((float*)C + (size_t)row0 * N + col) = make_float2(v0, v1);
                *reinterpret_cast<float2*>((float*)C + (size_t)(row0 + 8) * N + col) = make_float2(v2, v3);
            }
        }
    }
}

// ---------------------------------------------------------------------------
// Flash attention, fp16 mma.sync (m16n8k16), fp32 accum + softmax.
// Q,K,V,O fp16 [rows, E], row = token*B + b, channel = h*HD + d.
// grid = (L/128, H, B), block = 256 (8 warps); warp w owns q rows [16w,16w+16).
// Smem (bytes): Qs 128x128 | Ks 64x128 | Vs 64x128 | Ps 128x128 = 48 KB.
// All rows 128B, chunk-XOR swizzle. V read via ldmatrix.x2.trans (no transpose).
// ---------------------------------------------------------------------------
#define FL_KS (128 * 128)
#define FL_VS (FL_KS + 64 * 128)
#define FL_PS (FL_VS + 64 * 128)
#define FLASH_SMEM (FL_PS + 128 * 128)   // 49152 B

__global__ __launch_bounds__(256, 2) void flash_f16_kernel(
    const __half* __restrict__ Q, const __half* __restrict__ K,
    const __half* __restrict__ V, __half* __restrict__ O,
    int causal)
{
    extern __shared__ char fsm[];
    const uint32_t sb = smem_u32(fsm);

    const int tid = threadIdx.x;
    const int lane = tid & 31;
    const int wid = tid >> 5;
    const int g = lane >> 2, t4 = lane & 3;
    const int r8 = lane & 7, hi8 = (lane >> 3) & 1, hi16 = lane >> 4;
    const int qr = wid * 16;

    const int qb = blockIdx.x;
    const int h = blockIdx.y;
    const int b = blockIdx.z;

    // Load Q tile [128 x 64] fp16 (swizzled)
#pragma unroll
    for (int it = 0; it < 4; it++) {
        int f = tid + it * 256;
        int row = f >> 3, seg = f & 7;
        uint4 v = *reinterpret_cast<const uint4*>(
            &Q[((size_t)(qb * 128 + row) * BB + b) * EE + h * HD + seg * 8]);
        *reinterpret_cast<uint4*>(fsm + row * 128 + ((seg ^ (row & 7)) << 4)) = v;
    }

    // Fragment address bases
    const uint32_t baseQ = sb + (qr + r8 + 8 * hi8) * 128;
    const uint32_t baseP = sb + FL_PS + (qr + r8 + 8 * hi8) * 128;
    const uint32_t baseV0 = sb + FL_VS + (r8 + 8 * hi8) * 128;

    float o[8][4];
#pragma unroll
    for (int nt = 0; nt < 8; nt++)
#pragma unroll
        for (int r = 0; r < 4; r++) o[nt][r] = 0.0f;
    float m0_ = -1e30f, m1_ = -1e30f, l0_ = 0.0f, l1_ = 0.0f;

    const int nkt = causal ? (2 * qb + 2) : (SK / 64);

    for (int kt = 0; kt < nkt; kt++) {
        __syncthreads();  // prior-iter reads of Ks/Vs done; Qs published (iter 0)
        // Load K and V tiles [64 x 64] fp16
#pragma unroll
        for (int it = 0; it < 4; it++) {
            int f = tid + it * 256;
            int mat = f >> 9;            // 0 = K, 1 = V
            int row = (f >> 3) & 63, seg = f & 7;
            const __half* src = (mat ? V : K) +
                ((size_t)(kt * 64 + row) * BB + b) * EE + h * HD + seg * 8;
            uint4 v = *reinterpret_cast<const uint4*>(src);
            *reinterpret_cast<uint4*>(fsm + (mat ? FL_VS : FL_KS) +
                row * 128 + ((seg ^ (row & 7)) << 4)) = v;
        }
        __syncthreads();

        // S = Q K^T  (warp m16 x n64, k=64: 4 k16 steps)
        float s[8][4];
#pragma unroll
        for (int nt = 0; nt < 8; nt++)
#pragma unroll
            for (int r = 0; r < 4; r++) s[nt][r] = 0.0f;

#pragma unroll
        for (int ks = 0; ks < 4; ks++) {
            unsigned a[4];
            ldsm_x4(a, baseQ + (((ks * 2 + hi16) ^ r8) << 4));
            const int cB = ks * 2 + hi8;
#pragma unroll
            for (int nt = 0; nt < 8; nt++) {
                unsigned bf[2];
                ldsm_x2(bf, sb + FL_KS + (nt * 8 + r8) * 128 + ((cB ^ r8) << 4));
                mma_f16(s[nt], a, bf);
            }
        }

        // scale
#pragma unroll
        for (int nt = 0; nt < 8; nt++)
#pragma unroll
            for (int r = 0; r < 4; r++) s[nt][r] *= 0.125f;

        // Causal mask (diagonal-overlapping tiles only)
        if (causal && kt >= 2 * qb) {
            int row0 = qb * 128 + qr + g;
            int row1 = row0 + 8;
#pragma unroll
            for (int nt = 0; nt < 8; nt++) {
                int col = kt * 64 + nt * 8 + 2 * t4;
                if (col > row0)     s[nt][0] = -1e30f;
                if (col + 1 > row0) s[nt][1] = -1e30f;
                if (col > row1)     s[nt][2] = -1e30f;
                if (col + 1 > row1) s[nt][3] = -1e30f;
            }
        }

        // Online softmax (thread owns rows g, g+8)
        float mx0 = -1e30f, mx1 = -1e30f;
#pragma unroll
        for (int nt = 0; nt < 8; nt++) {
            mx0 = fmaxf(mx0, fmaxf(s[nt][0], s[nt][1]));
            mx1 = fmaxf(mx1, fmaxf(s[nt][2], s[nt][3]));
        }
        mx0 = fmaxf(mx0, __shfl_xor_sync(0xffffffffu, mx0, 1));
        mx0 = fmaxf(mx0, __shfl_xor_sync(0xffffffffu, mx0, 2));
        mx1 = fmaxf(mx1, __shfl_xor_sync(0xffffffffu, mx1, 1));
        mx1 = fmaxf(mx1, __shfl_xor_sync(0xffffffffu, mx1, 2));

        float nm0 = fmaxf(m0_, mx0);
        float nm1 = fmaxf(m1_, mx1);
        float corr0 = __expf(m0_ - nm0);
        float corr1 = __expf(m1_ - nm1);
        m0_ = nm0; m1_ = nm1;

        float sum0 = 0.0f, sum1 = 0.0f;
#pragma unroll
        for (int nt = 0; nt < 8; nt++) {
            s[nt][0] = __expf(s[nt][0] - nm0);
            s[nt][1] = __expf(s[nt][1] - nm0);
            s[nt][2] = __expf(s[nt][2] - nm1);
            s[nt][3] = __expf(s[nt][3] - nm1);
            sum0 += s[nt][0] + s[nt][1];
            sum1 += s[nt][2] + s[nt][3];
        }
        sum0 += __shfl_xor_sync(0xffffffffu, sum0, 1);
        sum0 += __shfl_xor_sync(0xffffffffu, sum0, 2);
        sum1 += __shfl_xor_sync(0xffffffffu, sum1, 1);
        sum1 += __shfl_xor_sync(0xffffffffu, sum1, 2);
        l0_ = l0_ * corr0 + sum0;
        l1_ = l1_ * corr1 + sum1;
#pragma unroll
        for (int nt = 0; nt < 8; nt++) {
            o[nt][0] *= corr0; o[nt][1] *= corr0;
            o[nt][2] *= corr1; o[nt][3] *= corr1;
        }

        // Store P fp16 (warp-private rows; swizzled chunks)
#pragma unroll
        for (int nt = 0; nt < 8; nt++) {
            char* p0 = fsm + FL_PS + (qr + g) * 128 + ((nt ^ g) << 4) + t4 * 4;
            char* p1 = fsm + FL_PS + (qr + g + 8) * 128 + ((nt ^ g) << 4) + t4 * 4;
            *reinterpret_cast<__half2*>(p0) = __floats2half2_rn(s[nt][0], s[nt][1]);
            *reinterpret_cast<__half2*>(p1) = __floats2half2_rn(s[nt][2], s[nt][3]);
        }
        __syncwarp();

        // O += P @ V  (A via ldmatrix.x4 on Ps; B via ldmatrix.x2.trans on Vs)
#pragma unroll
        for (int ks = 0; ks < 4; ks++) {
            unsigned a[4];
            ldsm_x4(a, baseP + (((ks * 2 + hi16) ^ r8) << 4));
            const uint32_t bv = baseV0 + ks * 16 * 128;
#pragma unroll
            for (int nt = 0; nt < 8; nt++) {
                unsigned bf[2];
                ldsm_x2t(bf, bv + ((nt ^ r8) << 4));
                mma_f16(o[nt], a, bf);
            }
        }
    }

    // Normalize + store fp16
    float inv0 = 1.0f / l0_;
    float inv1 = 1.0f / l1_;
    int tok0 = qb * 128 + qr + g;
#pragma unroll
    for (int nt = 0; nt < 8; nt++) {
        int col = h * HD + nt * 8 + 2 * t4;
        *reinterpret_cast<__half2*>(&O[((size_t)tok0 * BB + b) * EE + col]) =
            __floats2half2_rn(o[nt][0] * inv0, o[nt][1] * inv0);
        *reinterpret_cast<__half2*>(&O[((size_t)(tok0 + 8) * BB + b) * EE + col]) =
            __floats2half2_rn(o[nt][2] * inv1, o[nt][3] * inv1);
    }
}

// ---------------------------------------------------------------------------
// Fused add + LayerNorm: out = LN(x + y) * g + b (row length 1024).
// Optionally also writes an fp16 copy (out16 != nullptr).
// ---------------------------------------------------------------------------
__global__ __launch_bounds__(256) void add_ln_kernel(
    const float* __restrict__ X, const float* __restrict__ Y,
    const float* __restrict__ gamma, const float* __restrict__ beta,
    float* __restrict__ out, __half* __restrict__ out16)
{
    const int row = blockIdx.x;
    const int tid = threadIdx.x;
    const size_t base = (size_t)row * EE + tid * 4;

    float4 xv = *reinterpret_cast<const float4*>(&X[base]);
    float4 yv = *reinterpret_cast<const float4*>(&Y[base]);
    float v0 = xv.x + yv.x, v1 = xv.y + yv.y, v2 = xv.z + yv.z, v3 = xv.w + yv.w;

    float s1 = v0 + v1 + v2 + v3;
    float s2 = v0 * v0 + v1 * v1 + v2 * v2 + v3 * v3;

    __shared__ float sm1[8], sm2[8];
#pragma unroll
    for (int off = 16; off > 0; off >>= 1) {
        s1 += __shfl_xor_sync(0xffffffffu, s1, off);
        s2 += __shfl_xor_sync(0xffffffffu, s2, off);
    }
    int wid = tid >> 5, lid = tid & 31;
    if (lid == 0) { sm1[wid] = s1; sm2[wid] = s2; }
    __syncthreads();
    if (wid == 0) {
        s1 = (lid < 8) ? sm1[lid] : 0.0f;
        s2 = (lid < 8) ? sm2[lid] : 0.0f;
#pragma unroll
        for (int off = 4; off > 0; off >>= 1) {
            s1 += __shfl_xor_sync(0xffffffffu, s1, off);
            s2 += __shfl_xor_sync(0xffffffffu, s2, off);
        }
        if (lid == 0) { sm1[0] = s1; sm2[0] = s2; }
    }
    __syncthreads();
    float mean = sm1[0] * (1.0f / EE);
    float var = sm2[0] * (1.0f / EE) - mean * mean;
    float r = rsqrtf(var + 1e-5f);

    int c = tid * 4;
    float4 gv = *reinterpret_cast<const float4*>(&gamma[c]);
    float4 bv = *reinterpret_cast<const float4*>(&beta[c]);
    float4 ov;
    ov.x = (v0 - mean) * r * gv.x + bv.x;
    ov.y = (v1 - mean) * r * gv.y + bv.y;
    ov.z = (v2 - mean) * r * gv.z + bv.z;
    ov.w = (v3 - mean) * r * gv.w + bv.w;
    *reinterpret_cast<float4*>(&out[base]) = ov;
    if (out16) {
        *reinterpret_cast<__half2*>(out16 + base) = __floats2half2_rn(ov.x, ov.y);
        *reinterpret_cast<__half2*>(out16 + base + 2) = __floats2half2_rn(ov.z, ov.w);
    }
}

// ---------------------------------------------------------------------------
// Host orchestration
// ---------------------------------------------------------------------------
template <typename OutT, bool RELU>
static void launch_gemm(const __half* A, const __half* W, const float* bias,
                        OutT* C, int M, int N, int K)
{
    dim3 grid(N / 128, M / 128);
    gemm_f16_kernel<OutT, RELU><<<grid, 256, GEMM_SMEM>>>(A, W, bias, C, M, N, K);
}

static void cvt(const float* in, __half* out, int n)
{
    f2h_kernel<<<(n / 4 + 255) / 256, 256>>>(in, out, n);
}

extern "C" void kernel_launch(void* const* d_in, const int* in_sizes, int n_in,
                              void* d_out, int out_size)
{
    const float* tgt    = (const float*)d_in[0];
    const float* memory = (const float*)d_in[1];
    // d_in[2] = tgt_mask (causal; implemented directly)
    const float* sa_Wq = (const float*)d_in[3];
    const float* sa_bq = (const float*)d_in[4];
    const float* sa_Wk = (const float*)d_in[5];
    const float* sa_bk = (const float*)d_in[6];
    const float* sa_Wv = (const float*)d_in[7];
    const float* sa_bv = (const float*)d_in[8];
    const float* sa_Wo = (const float*)d_in[9];
    const float* sa_bo = (const float*)d_in[10];
    const float* ca_Wq = (const float*)d_in[11];
    const float* ca_bq = (const float*)d_in[12];
    const float* ca_Wk = (const float*)d_in[13];
    const float* ca_bk = (const float*)d_in[14];
    const float* ca_Wv = (const float*)d_in[15];
    const float* ca_bv = (const float*)d_in[16];
    const float* ca_Wo = (const float*)d_in[17];
    const float* ca_bo = (const float*)d_in[18];
    const float* W1    = (const float*)d_in[19];
    const float* b1    = (const float*)d_in[20];
    const float* W2    = (const float*)d_in[21];
    const float* b2    = (const float*)d_in[22];
    const float* ln1_g = (const float*)d_in[23];
    const float* ln1_b = (const float*)d_in[24];
    const float* ln2_g = (const float*)d_in[25];
    const float* ln2_b = (const float*)d_in[26];
    const float* ln3_g = (const float*)d_in[27];
    const float* ln3_b = (const float*)d_in[28];
    float* out = (float*)d_out;

    __half *pWsaq, *pWsak, *pWsav, *pWsao, *pWcaq, *pWcak, *pWcav, *pWcao;
    __half *pW1, *pW2, *pTgt, *pMem, *pQ, *pK, *pV, *pA, *pX, *pH;
    float *pO, *pX1, *pX2;
    cudaGetSymbolAddress((void**)&pWsaq, hW_saq);
    cudaGetSymbolAddress((void**)&pWsak, hW_sak);
    cudaGetSymbolAddress((void**)&pWsav, hW_sav);
    cudaGetSymbolAddress((void**)&pWsao, hW_sao);
    cudaGetSymbolAddress((void**)&pWcaq, hW_caq);
    cudaGetSymbolAddress((void**)&pWcak, hW_cak);
    cudaGetSymbolAddress((void**)&pWcav, hW_cav);
    cudaGetSymbolAddress((void**)&pWcao, hW_cao);
    cudaGetSymbolAddress((void**)&pW1, hW1);
    cudaGetSymbolAddress((void**)&pW2, hW2);
    cudaGetSymbolAddress((void**)&pTgt, h_tgt);
    cudaGetSymbolAddress((void**)&pMem, h_mem);
    cudaGetSymbolAddress((void**)&pQ, h_Q);
    cudaGetSymbolAddress((void**)&pK, h_K);
    cudaGetSymbolAddress((void**)&pV, h_V);
    cudaGetSymbolAddress((void**)&pA, h_A);
    cudaGetSymbolAddress((void**)&pX, h_X);
    cudaGetSymbolAddress((void**)&pH, h_H);
    cudaGetSymbolAddress((void**)&pO, f_O);
    cudaGetSymbolAddress((void**)&pX1, f_X1);
    cudaGetSymbolAddress((void**)&pX2, f_X2);

    cudaFuncSetAttribute(gemm_f16_kernel<float, false>,
                         cudaFuncAttributeMaxDynamicSharedMemorySize, GEMM_SMEM);
    cudaFuncSetAttribute(gemm_f16_kernel<__half, false>,
                         cudaFuncAttributeMaxDynamicSharedMemorySize, GEMM_SMEM);
    cudaFuncSetAttribute(gemm_f16_kernel<__half, true>,
                         cudaFuncAttributeMaxDynamicSharedMemorySize, GEMM_SMEM);
    cudaFuncSetAttribute(flash_f16_kernel,
                         cudaFuncAttributeMaxDynamicSharedMemorySize, FLASH_SMEM);

    // ---- Convert weights + inputs to fp16 ----
    cvt(sa_Wq, pWsaq, EE * EE); cvt(sa_Wk, pWsak, EE * EE);
    cvt(sa_Wv, pWsav, EE * EE); cvt(sa_Wo, pWsao, EE * EE);
    cvt(ca_Wq, pWcaq, EE * EE); cvt(ca_Wk, pWcak, EE * EE);
    cvt(ca_Wv, pWcav, EE * EE); cvt(ca_Wo, pWcao, EE * EE);
    cvt(W1, pW1, FF * EE); cvt(W2, pW2, EE * FF);
    cvt(tgt, pTgt, MM * EE); cvt(memory, pMem, MM * EE);

    dim3 attn_grid(LQ / 128, HH, BB);

    // ---- Self-attention block ----
    launch_gemm<__half, false>(pTgt, pWsaq, sa_bq, pQ, MM, EE, EE);
    launch_gemm<__half, false>(pTgt, pWsak, sa_bk, pK, MM, EE, EE);
    launch_gemm<__half, false>(pTgt, pWsav, sa_bv, pV, MM, EE, EE);
    flash_f16_kernel<<<attn_grid, 256, FLASH_SMEM>>>(pQ, pK, pV, pA, 1);
    launch_gemm<float, false>(pA, pWsao, sa_bo, pO, MM, EE, EE);
    add_ln_kernel<<<MM, 256>>>(tgt, pO, ln1_g, ln1_b, pX1, pX);

    // ---- Cross-attention block ----
    launch_gemm<__half, false>(pX, pWcaq, ca_bq, pQ, MM, EE, EE);
    launch_gemm<__half, false>(pMem, pWcak, ca_bk, pK, MM, EE, EE);
    launch_gemm<__half, false>(pMem, pWcav, ca_bv, pV, MM, EE, EE);
    flash_f16_kernel<<<attn_grid, 256, FLASH_SMEM>>>(pQ, pK, pV, pA, 0);
    launch_gemm<float, false>(pA, pWcao, ca_bo, pO, MM, EE, EE);
    add_ln_kernel<<<MM, 256>>>(pX1, pO, ln2_g, ln2_b, pX2, pX);

    // ---- FFN block ----
    launch_gemm<__half, true>(pX, pW1, b1, pH, MM, FF, EE);
    launch_gemm<float, false>(pH, pW2, b2, pO, MM, EE, FF);
    add_ln_kernel<<<MM, 256>>>(pX2, pO, ln3_g, ln3_b, out, nullptr);
}

// round 10
// speedup vs baseline: 8.5776x; 1.0831x over previous
#include <cuda_runtime.h>
#include <cuda_fp16.h>
#include <cstdint>

// Problem constants
#define LQ 2048
#define SK 2048
#define BB 4
#define EE 1024
#define HH 16
#define HD 64
#define FF 4096
#define MM (LQ * BB)   // 8192 rows

// ---------------------------------------------------------------------------
// Scratch buffers (__device__ globals: allocation-free per harness rules)
// ---------------------------------------------------------------------------
__device__ __half hW_saq[EE * EE], hW_sak[EE * EE], hW_sav[EE * EE], hW_sao[EE * EE];
__device__ __half hW_caq[EE * EE], hW_cak[EE * EE], hW_cav[EE * EE], hW_cao[EE * EE];
__device__ __half hW1[FF * EE], hW2[EE * FF];
__device__ __half h_tgt[MM * EE], h_mem[MM * EE];
__device__ __half h_Q[MM * EE], h_K[MM * EE], h_V[MM * EE], h_A[MM * EE];
__device__ __half h_X[MM * EE];
__device__ __half h_H[MM * FF];
__device__ float f_O[MM * EE], f_X1[MM * EE], f_X2[MM * EE];

// ---------------------------------------------------------------------------
// Helpers
// ---------------------------------------------------------------------------
__device__ __forceinline__ uint32_t smem_u32(const void* p) {
    uint32_t a;
    asm("{ .reg .u64 t; cvta.to.shared.u64 t, %1; cvt.u32.u64 %0, t; }"
        : "=r"(a) : "l"(p));
    return a;
}

__device__ __forceinline__ void mma_f16(float* c, const unsigned* a, const unsigned* b) {
    asm volatile(
        "mma.sync.aligned.m16n8k16.row.col.f32.f16.f16.f32 "
        "{%0,%1,%2,%3}, {%4,%5,%6,%7}, {%8,%9}, {%0,%1,%2,%3};\n"
        : "+f"(c[0]), "+f"(c[1]), "+f"(c[2]), "+f"(c[3])
        : "r"(a[0]), "r"(a[1]), "r"(a[2]), "r"(a[3]), "r"(b[0]), "r"(b[1]));
}

__device__ __forceinline__ void ldsm_x4(unsigned* r, uint32_t addr) {
    asm volatile("ldmatrix.sync.aligned.m8n8.x4.shared.b16 {%0,%1,%2,%3}, [%4];\n"
        : "=r"(r[0]), "=r"(r[1]), "=r"(r[2]), "=r"(r[3]) : "r"(addr));
}
__device__ __forceinline__ void ldsm_x2(unsigned* r, uint32_t addr) {
    asm volatile("ldmatrix.sync.aligned.m8n8.x2.shared.b16 {%0,%1}, [%2];\n"
        : "=r"(r[0]), "=r"(r[1]) : "r"(addr));
}
__device__ __forceinline__ void ldsm_x2t(unsigned* r, uint32_t addr) {
    asm volatile("ldmatrix.sync.aligned.m8n8.x2.trans.shared.b16 {%0,%1}, [%2];\n"
        : "=r"(r[0]), "=r"(r[1]) : "r"(addr));
}

__device__ __forceinline__ void cp_async16s(uint32_t daddr, const void* src) {
    asm volatile("cp.async.cg.shared.global [%0], [%1], 16;\n" :: "r"(daddr), "l"(src));
}

// ---------------------------------------------------------------------------
// fp32 -> fp16 convert (rne)
// ---------------------------------------------------------------------------
__global__ __launch_bounds__(256) void f2h_kernel(
    const float* __restrict__ in, __half* __restrict__ out, int n)
{
    int i = (blockIdx.x * 256 + threadIdx.x) * 4;
    if (i < n) {
        float4 v = *reinterpret_cast<const float4*>(in + i);
        *reinterpret_cast<__half2*>(out + i) = __floats2half2_rn(v.x, v.y);
        *reinterpret_cast<__half2*>(out + i + 2) = __floats2half2_rn(v.z, v.w);
    }
}

// ---------------------------------------------------------------------------
// FP16 tensor-core GEMM (mma.sync m16n8k16), fp32 accumulate.
// C[M,N] = ((A[M,K] @ W[N,K]^T) + bias) * outscale, optional ReLU.
// Block tile 128x256, BK=64 halves, 256 threads = 8 warps (2x4),
// warp tile 64x64. 3-stage cp.async pipeline. Smem rows: 128B data,
// chunk-XOR swizzle (chunk ^= row&7) -> conflict-free ldmatrix + STS.
// ---------------------------------------------------------------------------
#define GT_A_B (128 * 128)                  // A tile bytes
#define GT_B_B (256 * 128)                  // W tile bytes
#define GEMM_STAGE_B (GT_A_B + GT_B_B)      // 49152
#define GEMM_SMEM (3 * GEMM_STAGE_B)        // 147456 B

template <typename OutT, bool RELU>
__global__ __launch_bounds__(256, 1) void gemm_f16_kernel(
    const __half* __restrict__ A, const __half* __restrict__ W,
    const float* __restrict__ bias, OutT* __restrict__ C,
    int M, int N, int K, float outscale)
{
    extern __shared__ char gsm[];
    const uint32_t sb = smem_u32(gsm);

    const int tid = threadIdx.x;
    const int lane = tid & 31;
    const int wid = tid >> 5;
    const int wm = wid >> 2, wn = wid & 3;
    const int g = lane >> 2, t4 = lane & 3;
    const int r8 = lane & 7, hi8 = (lane >> 3) & 1, hi16 = lane >> 4;

    const int m0 = blockIdx.y * 128;
    const int n0 = blockIdx.x * 256;

    int rowOffA[4], rowOffB[8];
#pragma unroll
    for (int mt = 0; mt < 4; mt++)
        rowOffA[mt] = (wm * 64 + mt * 16 + r8 + 8 * hi8) * 128;
#pragma unroll
    for (int nt = 0; nt < 8; nt++)
        rowOffB[nt] = GT_A_B + (wn * 64 + nt * 8 + r8) * 128;

    float acc[4][8][4];
#pragma unroll
    for (int mt = 0; mt < 4; mt++)
#pragma unroll
        for (int nt = 0; nt < 8; nt++)
#pragma unroll
            for (int r = 0; r < 4; r++) acc[mt][nt][r] = 0.0f;

    const int lrow = tid >> 3;      // 0..31
    const int lseg = tid & 7;       // 16B chunk

    auto load_stage = [&](int st, int kb) {
        uint32_t base = sb + st * GEMM_STAGE_B;
        const __half* ag = A + (size_t)(m0 + lrow) * K + kb * 64 + lseg * 8;
#pragma unroll
        for (int it = 0; it < 4; it++) {
            int row = lrow + it * 32;
            cp_async16s(base + row * 128 + ((lseg ^ (row & 7)) << 4),
                        ag + (size_t)(it * 32) * K);
        }
        const __half* wg = W + (size_t)(n0 + lrow) * K + kb * 64 + lseg * 8;
#pragma unroll
        for (int it = 0; it < 8; it++) {
            int row = lrow + it * 32;
            cp_async16s(base + GT_A_B + row * 128 + ((lseg ^ (row & 7)) << 4),
                        wg + (size_t)(it * 32) * K);
        }
        asm volatile("cp.async.commit_group;\n" ::: "memory");
    };

    const int NK = K >> 6;   // BK = 64 halves

    load_stage(0, 0);
    load_stage(1, 1);
    load_stage(2, 2);

    for (int kb = 0; kb < NK; kb++) {
        if (kb < NK - 2)       asm volatile("cp.async.wait_group 2;\n" ::: "memory");
        else if (kb == NK - 2) asm volatile("cp.async.wait_group 1;\n" ::: "memory");
        else                   asm volatile("cp.async.wait_group 0;\n" ::: "memory");
        __syncthreads();

        const uint32_t sa = sb + (kb % 3) * GEMM_STAGE_B;

#pragma unroll
        for (int ks = 0; ks < 4; ks++) {
            unsigned a[4][4], bf[8][2];
            const int cA = ks * 2 + hi16;
            const int cB = ks * 2 + hi8;
#pragma unroll
            for (int mt = 0; mt < 4; mt++)
                ldsm_x4(a[mt], sa + rowOffA[mt] + ((cA ^ r8) << 4));
#pragma unroll
            for (int nt = 0; nt < 8; nt++)
                ldsm_x2(bf[nt], sa + rowOffB[nt] + ((cB ^ r8) << 4));
#pragma unroll
            for (int mt = 0; mt < 4; mt++)
#pragma unroll
                for (int nt = 0; nt < 8; nt++)
                    mma_f16(acc[mt][nt], a[mt], bf[nt]);
        }

        if (kb + 3 < NK) {
            __syncthreads();   // all warps done reading stage kb%3
            load_stage(kb % 3, kb + 3);
        }
    }

    // Epilogue
#pragma unroll
    for (int mt = 0; mt < 4; mt++) {
        int row0 = m0 + wm * 64 + mt * 16 + g;
#pragma unroll
        for (int nt = 0; nt < 8; nt++) {
            int col = n0 + wn * 64 + nt * 8 + 2 * t4;
            float b0 = bias[col], b1 = bias[col + 1];
            float v0 = (acc[mt][nt][0] + b0) * outscale;
            float v1 = (acc[mt][nt][1] + b1) * outscale;
            float v2 = (acc[mt][nt][2] + b0) * outscale;
            float v3 = (acc[mt][nt][3] + b1) * outscale;
            if (RELU) {
                v0 = fmaxf(v0, 0.0f); v1 = fmaxf(v1, 0.0f);
                v2 = fmaxf(v2, 0.0f); v3 = fmaxf(v3, 0.0f);
            }
            if (sizeof(OutT) == 2) {
                *reinterpret_cast<__half2*>((__half*)C + (size_t)row0 * N + col) =
                    __floats2half2_rn(v0, v1);
                *reinterpret_cast<__half2*>((__half*)C + (size_t)(row0 + 8) * N + col) =
                    __floats2half2_rn(v2, v3);
            } else {
                *reinterpret_cast<float2*>((float*)C + (size_t)row0 * N + col) =
                    make_float2(v0, v1);
                *reinterpret_cast<float2*>((float*)C + (size_t)(row0 + 8) * N + col) =
                    make_float2(v2, v3);
            }
        }
    }
}

// ---------------------------------------------------------------------------
// Flash attention, fp16 mma.sync, fp32 accum, base-2 softmax.
// Q is PRE-SCALED by 0.125*log2(e) in the projection epilogue, so
// p = exp2(s - m) == softmax numerator with the 1/sqrt(64) scale.
// grid = (L/128, H, B), block = 256 (8 warps); warp w owns q rows [16w,16w+16).
// K/V double-buffered via cp.async (prefetch tile kt+1 during compute of kt).
// Smem: Qs 16K | Ks[2] 8K each | Vs[2] 8K each | Ps 16K = 64 KB.
// ---------------------------------------------------------------------------
#define FL_K0 16384
#define FL_V0 (16384 + 2 * 8192)
#define FL_PS (FL_V0 + 2 * 8192)
#define FLASH_SMEM (FL_PS + 128 * 128)   // 65536 B

__global__ __launch_bounds__(256, 2) void flash_f16_kernel(
    const __half* __restrict__ Q, const __half* __restrict__ K,
    const __half* __restrict__ V, __half* __restrict__ O,
    int causal)
{
    extern __shared__ char fsm[];
    const uint32_t sb = smem_u32(fsm);

    const int tid = threadIdx.x;
    const int lane = tid & 31;
    const int wid = tid >> 5;
    const int g = lane >> 2, t4 = lane & 3;
    const int r8 = lane & 7, hi8 = (lane >> 3) & 1, hi16 = lane >> 4;
    const int qr = wid * 16;

    const int qb = blockIdx.x;
    const int h = blockIdx.y;
    const int b = blockIdx.z;

    // Load Q tile [128 x 64] fp16 (swizzled)
#pragma unroll
    for (int it = 0; it < 4; it++) {
        int f = tid + it * 256;
        int row = f >> 3, seg = f & 7;
        uint4 v = *reinterpret_cast<const uint4*>(
            &Q[((size_t)(qb * 128 + row) * BB + b) * EE + h * HD + seg * 8]);
        *reinterpret_cast<uint4*>(fsm + row * 128 + ((seg ^ (row & 7)) << 4)) = v;
    }

    const uint32_t baseQ = sb + (qr + r8 + 8 * hi8) * 128;
    const uint32_t baseP = sb + FL_PS + (qr + r8 + 8 * hi8) * 128;

    auto load_kv = [&](int buf, int kt) {
#pragma unroll
        for (int it = 0; it < 4; it++) {
            int f = tid + it * 256;
            int mat = f >> 9;            // 0 = K, 1 = V
            int row = (f >> 3) & 63, seg = f & 7;
            const __half* src = (mat ? V : K) +
                ((size_t)(kt * 64 + row) * BB + b) * EE + h * HD + seg * 8;
            cp_async16s(sb + (mat ? FL_V0 : FL_K0) + buf * 8192 +
                        row * 128 + ((seg ^ (row & 7)) << 4), src);
        }
        asm volatile("cp.async.commit_group;\n" ::: "memory");
    };

    float o[8][4];
#pragma unroll
    for (int nt = 0; nt < 8; nt++)
#pragma unroll
        for (int r = 0; r < 4; r++) o[nt][r] = 0.0f;
    float m0_ = -1e30f, m1_ = -1e30f, l0_ = 0.0f, l1_ = 0.0f;

    const int nkt = causal ? (2 * qb + 2) : (SK / 64);

    load_kv(0, 0);

    for (int kt = 0; kt < nkt; kt++) {
        asm volatile("cp.async.wait_group 0;\n" ::: "memory");
        __syncthreads();   // K/V(kt) visible; prior reads of other buffer done
        if (kt + 1 < nkt) load_kv((kt + 1) & 1, kt + 1);

        const uint32_t sk = sb + FL_K0 + (kt & 1) * 8192;
        const uint32_t sv = sb + FL_V0 + (kt & 1) * 8192 + (r8 + 8 * hi8) * 128;

        // S = Q K^T  (warp m16 x n64, k=64: 4 k16 steps)
        float s[8][4];
#pragma unroll
        for (int nt = 0; nt < 8; nt++)
#pragma unroll
            for (int r = 0; r < 4; r++) s[nt][r] = 0.0f;

#pragma unroll
        for (int ks = 0; ks < 4; ks++) {
            unsigned a[4];
            ldsm_x4(a, baseQ + (((ks * 2 + hi16) ^ r8) << 4));
            const int cB = ks * 2 + hi8;
#pragma unroll
            for (int nt = 0; nt < 8; nt++) {
                unsigned bf[2];
                ldsm_x2(bf, sk + (nt * 8 + r8) * 128 + ((cB ^ r8) << 4));
                mma_f16(s[nt], a, bf);
            }
        }

        // Causal mask (diagonal-overlapping tiles only)
        if (causal && kt >= 2 * qb) {
            int row0 = qb * 128 + qr + g;
            int row1 = row0 + 8;
#pragma unroll
            for (int nt = 0; nt < 8; nt++) {
                int col = kt * 64 + nt * 8 + 2 * t4;
                if (col > row0)     s[nt][0] = -1e30f;
                if (col + 1 > row0) s[nt][1] = -1e30f;
                if (col > row1)     s[nt][2] = -1e30f;
                if (col + 1 > row1) s[nt][3] = -1e30f;
            }
        }

        // Online softmax, base 2 (thread owns rows g, g+8)
        float mx0 = -1e30f, mx1 = -1e30f;
#pragma unroll
        for (int nt = 0; nt < 8; nt++) {
            mx0 = fmaxf(mx0, fmaxf(s[nt][0], s[nt][1]));
            mx1 = fmaxf(mx1, fmaxf(s[nt][2], s[nt][3]));
        }
        mx0 = fmaxf(mx0, __shfl_xor_sync(0xffffffffu, mx0, 1));
        mx0 = fmaxf(mx0, __shfl_xor_sync(0xffffffffu, mx0, 2));
        mx1 = fmaxf(mx1, __shfl_xor_sync(0xffffffffu, mx1, 1));
        mx1 = fmaxf(mx1, __shfl_xor_sync(0xffffffffu, mx1, 2));

        float nm0 = fmaxf(m0_, mx0);
        float nm1 = fmaxf(m1_, mx1);
        float corr0 = exp2f(m0_ - nm0);
        float corr1 = exp2f(m1_ - nm1);
        m0_ = nm0; m1_ = nm1;

        float sum0 = 0.0f, sum1 = 0.0f;
#pragma unroll
        for (int nt = 0; nt < 8; nt++) {
            s[nt][0] = exp2f(s[nt][0] - nm0);
            s[nt][1] = exp2f(s[nt][1] - nm0);
            s[nt][2] = exp2f(s[nt][2] - nm1);
            s[nt][3] = exp2f(s[nt][3] - nm1);
            sum0 += s[nt][0] + s[nt][1];
            sum1 += s[nt][2] + s[nt][3];
        }
        sum0 += __shfl_xor_sync(0xffffffffu, sum0, 1);
        sum0 += __shfl_xor_sync(0xffffffffu, sum0, 2);
        sum1 += __shfl_xor_sync(0xffffffffu, sum1, 1);
        sum1 += __shfl_xor_sync(0xffffffffu, sum1, 2);
        l0_ = l0_ * corr0 + sum0;
        l1_ = l1_ * corr1 + sum1;
#pragma unroll
        for (int nt = 0; nt < 8; nt++) {
            o[nt][0] *= corr0; o[nt][1] *= corr0;
            o[nt][2] *= corr1; o[nt][3] *= corr1;
        }

        // Store P fp16 (warp-private rows; swizzled chunks)
#pragma unroll
        for (int nt = 0; nt < 8; nt++) {
            char* p0 = fsm + FL_PS + (qr + g) * 128 + ((nt ^ g) << 4) + t4 * 4;
            char* p1 = fsm + FL_PS + (qr + g + 8) * 128 + ((nt ^ g) << 4) + t4 * 4;
            *reinterpret_cast<__half2*>(p0) = __floats2half2_rn(s[nt][0], s[nt][1]);
            *reinterpret_cast<__half2*>(p1) = __floats2half2_rn(s[nt][2], s[nt][3]);
        }
        __syncwarp();

        // O += P @ V
#pragma unroll
        for (int ks = 0; ks < 4; ks++) {
            unsigned a[4];
            ldsm_x4(a, baseP + (((ks * 2 + hi16) ^ r8) << 4));
            const uint32_t bv = sv + ks * 16 * 128;
#pragma unroll
            for (int nt = 0; nt < 8; nt++) {
                unsigned bf[2];
                ldsm_x2t(bf, bv + ((nt ^ r8) << 4));
                mma_f16(o[nt], a, bf);
            }
        }
    }

    // Normalize + store fp16
    float inv0 = 1.0f / l0_;
    float inv1 = 1.0f / l1_;
    int tok0 = qb * 128 + qr + g;
#pragma unroll
    for (int nt = 0; nt < 8; nt++) {
        int col = h * HD + nt * 8 + 2 * t4;
        *reinterpret_cast<__half2*>(&O[((size_t)tok0 * BB + b) * EE + col]) =
            __floats2half2_rn(o[nt][0] * inv0, o[nt][1] * inv0);
        *reinterpret_cast<__half2*>(&O[((size_t)(tok0 + 8) * BB + b) * EE + col]) =
            __floats2half2_rn(o[nt][2] * inv1, o[nt][3] * inv1);
    }
}

// ---------------------------------------------------------------------------
// Fused add + LayerNorm: out = LN(x + y) * g + b (row length 1024).
// Optionally also writes an fp16 copy (out16 != nullptr).
// ---------------------------------------------------------------------------
__global__ __launch_bounds__(256) void add_ln_kernel(
    const float* __restrict__ X, const float* __restrict__ Y,
    const float* __restrict__ gamma, const float* __restrict__ beta,
    float* __restrict__ out, __half* __restrict__ out16)
{
    const int row = blockIdx.x;
    const int tid = threadIdx.x;
    const size_t base = (size_t)row * EE + tid * 4;

    float4 xv = *reinterpret_cast<const float4*>(&X[base]);
    float4 yv = *reinterpret_cast<const float4*>(&Y[base]);
    float v0 = xv.x + yv.x, v1 = xv.y + yv.y, v2 = xv.z + yv.z, v3 = xv.w + yv.w;

    float s1 = v0 + v1 + v2 + v3;
    float s2 = v0 * v0 + v1 * v1 + v2 * v2 + v3 * v3;

    __shared__ float sm1[8], sm2[8];
#pragma unroll
    for (int off = 16; off > 0; off >>= 1) {
        s1 += __shfl_xor_sync(0xffffffffu, s1, off);
        s2 += __shfl_xor_sync(0xffffffffu, s2, off);
    }
    int wid = tid >> 5, lid = tid & 31;
    if (lid == 0) { sm1[wid] = s1; sm2[wid] = s2; }
    __syncthreads();
    if (wid == 0) {
        s1 = (lid < 8) ? sm1[lid] : 0.0f;
        s2 = (lid < 8) ? sm2[lid] : 0.0f;
#pragma unroll
        for (int off = 4; off > 0; off >>= 1) {
            s1 += __shfl_xor_sync(0xffffffffu, s1, off);
            s2 += __shfl_xor_sync(0xffffffffu, s2, off);
        }
        if (lid == 0) { sm1[0] = s1; sm2[0] = s2; }
    }
    __syncthreads();
    float mean = sm1[0] * (1.0f / EE);
    float var = sm2[0] * (1.0f / EE) - mean * mean;
    float r = rsqrtf(var + 1e-5f);

    int c = tid * 4;
    float4 gv = *reinterpret_cast<const float4*>(&gamma[c]);
    float4 bv = *reinterpret_cast<const float4*>(&beta[c]);
    float4 ov;
    ov.x = (v0 - mean) * r * gv.x + bv.x;
    ov.y = (v1 - mean) * r * gv.y + bv.y;
    ov.z = (v2 - mean) * r * gv.z + bv.z;
    ov.w = (v3 - mean) * r * gv.w + bv.w;
    *reinterpret_cast<float4*>(&out[base]) = ov;
    if (out16) {
        *reinterpret_cast<__half2*>(out16 + base) = __floats2half2_rn(ov.x, ov.y);
        *reinterpret_cast<__half2*>(out16 + base + 2) = __floats2half2_rn(ov.z, ov.w);
    }
}

// ---------------------------------------------------------------------------
// Host orchestration
// ---------------------------------------------------------------------------
#define QSCALE (0.125f * 1.4426950408889634f)   // 1/sqrt(HD) * log2(e)

template <typename OutT, bool RELU>
static void launch_gemm(const __half* A, const __half* W, const float* bias,
                        OutT* C, int M, int N, int K, float outscale = 1.0f)
{
    dim3 grid(N / 256, M / 128);
    gemm_f16_kernel<OutT, RELU><<<grid, 256, GEMM_SMEM>>>(A, W, bias, C, M, N, K, outscale);
}

static void cvt(const float* in, __half* out, int n)
{
    f2h_kernel<<<(n / 4 + 255) / 256, 256>>>(in, out, n);
}

extern "C" void kernel_launch(void* const* d_in, const int* in_sizes, int n_in,
                              void* d_out, int out_size)
{
    const float* tgt    = (const float*)d_in[0];
    const float* memory = (const float*)d_in[1];
    // d_in[2] = tgt_mask (causal; implemented directly)
    const float* sa_Wq = (const float*)d_in[3];
    const float* sa_bq = (const float*)d_in[4];
    const float* sa_Wk = (const float*)d_in[5];
    const float* sa_bk = (const float*)d_in[6];
    const float* sa_Wv = (const float*)d_in[7];
    const float* sa_bv = (const float*)d_in[8];
    const float* sa_Wo = (const float*)d_in[9];
    const float* sa_bo = (const float*)d_in[10];
    const float* ca_Wq = (const float*)d_in[11];
    const float* ca_bq = (const float*)d_in[12];
    const float* ca_Wk = (const float*)d_in[13];
    const float* ca_bk = (const float*)d_in[14];
    const float* ca_Wv = (const float*)d_in[15];
    const float* ca_bv = (const float*)d_in[16];
    const float* ca_Wo = (const float*)d_in[17];
    const float* ca_bo = (const float*)d_in[18];
    const float* W1    = (const float*)d_in[19];
    const float* b1    = (const float*)d_in[20];
    const float* W2    = (const float*)d_in[21];
    const float* b2    = (const float*)d_in[22];
    const float* ln1_g = (const float*)d_in[23];
    const float* ln1_b = (const float*)d_in[24];
    const float* ln2_g = (const float*)d_in[25];
    const float* ln2_b = (const float*)d_in[26];
    const float* ln3_g = (const float*)d_in[27];
    const float* ln3_b = (const float*)d_in[28];
    float* out = (float*)d_out;

    __half *pWsaq, *pWsak, *pWsav, *pWsao, *pWcaq, *pWcak, *pWcav, *pWcao;
    __half *pW1, *pW2, *pTgt, *pMem, *pQ, *pK, *pV, *pA, *pX, *pH;
    float *pO, *pX1, *pX2;
    cudaGetSymbolAddress((void**)&pWsaq, hW_saq);
    cudaGetSymbolAddress((void**)&pWsak, hW_sak);
    cudaGetSymbolAddress((void**)&pWsav, hW_sav);
    cudaGetSymbolAddress((void**)&pWsao, hW_sao);
    cudaGetSymbolAddress((void**)&pWcaq, hW_caq);
    cudaGetSymbolAddress((void**)&pWcak, hW_cak);
    cudaGetSymbolAddress((void**)&pWcav, hW_cav);
    cudaGetSymbolAddress((void**)&pWcao, hW_cao);
    cudaGetSymbolAddress((void**)&pW1, hW1);
    cudaGetSymbolAddress((void**)&pW2, hW2);
    cudaGetSymbolAddress((void**)&pTgt, h_tgt);
    cudaGetSymbolAddress((void**)&pMem, h_mem);
    cudaGetSymbolAddress((void**)&pQ, h_Q);
    cudaGetSymbolAddress((void**)&pK, h_K);
    cudaGetSymbolAddress((void**)&pV, h_V);
    cudaGetSymbolAddress((void**)&pA, h_A);
    cudaGetSymbolAddress((void**)&pX, h_X);
    cudaGetSymbolAddress((void**)&pH, h_H);
    cudaGetSymbolAddress((void**)&pO, f_O);
    cudaGetSymbolAddress((void**)&pX1, f_X1);
    cudaGetSymbolAddress((void**)&pX2, f_X2);

    cudaFuncSetAttribute(gemm_f16_kernel<float, false>,
                         cudaFuncAttributeMaxDynamicSharedMemorySize, GEMM_SMEM);
    cudaFuncSetAttribute(gemm_f16_kernel<__half, false>,
                         cudaFuncAttributeMaxDynamicSharedMemorySize, GEMM_SMEM);
    cudaFuncSetAttribute(gemm_f16_kernel<__half, true>,
                         cudaFuncAttributeMaxDynamicSharedMemorySize, GEMM_SMEM);
    cudaFuncSetAttribute(flash_f16_kernel,
                         cudaFuncAttributeMaxDynamicSharedMemorySize, FLASH_SMEM);

    // ---- Convert weights + inputs to fp16 ----
    cvt(sa_Wq, pWsaq, EE * EE); cvt(sa_Wk, pWsak, EE * EE);
    cvt(sa_Wv, pWsav, EE * EE); cvt(sa_Wo, pWsao, EE * EE);
    cvt(ca_Wq, pWcaq, EE * EE); cvt(ca_Wk, pWcak, EE * EE);
    cvt(ca_Wv, pWcav, EE * EE); cvt(ca_Wo, pWcao, EE * EE);
    cvt(W1, pW1, FF * EE); cvt(W2, pW2, EE * FF);
    cvt(tgt, pTgt, MM * EE); cvt(memory, pMem, MM * EE);

    dim3 attn_grid(LQ / 128, HH, BB);

    // ---- Self-attention block ----
    launch_gemm<__half, false>(pTgt, pWsaq, sa_bq, pQ, MM, EE, EE, QSCALE);
    launch_gemm<__half, false>(pTgt, pWsak, sa_bk, pK, MM, EE, EE);
    launch_gemm<__half, false>(pTgt, pWsav, sa_bv, pV, MM, EE, EE);
    flash_f16_kernel<<<attn_grid, 256, FLASH_SMEM>>>(pQ, pK, pV, pA, 1);
    launch_gemm<float, false>(pA, pWsao, sa_bo, pO, MM, EE, EE);
    add_ln_kernel<<<MM, 256>>>(tgt, pO, ln1_g, ln1_b, pX1, pX);

    // ---- Cross-attention block ----
    launch_gemm<__half, false>(pX, pWcaq, ca_bq, pQ, MM, EE, EE, QSCALE);
    launch_gemm<__half, false>(pMem, pWcak, ca_bk, pK, MM, EE, EE);
    launch_gemm<__half, false>(pMem, pWcav, ca_bv, pV, MM, EE, EE);
    flash_f16_kernel<<<attn_grid, 256, FLASH_SMEM>>>(pQ, pK, pV, pA, 0);
    launch_gemm<float, false>(pA, pWcao, ca_bo, pO, MM, EE, EE);
    add_ln_kernel<<<MM, 256>>>(pX1, pO, ln2_g, ln2_b, pX2, pX);

    // ---- FFN block ----
    launch_gemm<__half, true>(pX, pW1, b1, pH, MM, FF, EE);
    launch_gemm<float, false>(pH, pW2, b2, pO, MM, EE, FF);
    add_ln_kernel<<<MM, 256>>>(pX2, pO, ln3_g, ln3_b, out, nullptr);
}

// round 14
// speedup vs baseline: 9.0495x; 1.0550x over previous
#include <cuda_runtime.h>
#include <cuda_fp16.h>
#include <cstdint>

// Problem constants
#define LQ 2048
#define SK 2048
#define BB 4
#define EE 1024
#define HH 16
#define HD 64
#define FF 4096
#define MM (LQ * BB)   // 8192 rows

// ---------------------------------------------------------------------------
// Scratch buffers (__device__ globals: allocation-free per harness rules)
// ---------------------------------------------------------------------------
__device__ __half hW_saq[EE * EE], hW_sak[EE * EE], hW_sav[EE * EE], hW_sao[EE * EE];
__device__ __half hW_caq[EE * EE], hW_cak[EE * EE], hW_cav[EE * EE], hW_cao[EE * EE];
__device__ __half hW1[FF * EE], hW2[EE * FF];
__device__ __half h_tgt[MM * EE], h_mem[MM * EE];
__device__ __half h_Q[MM * EE], h_K[MM * EE], h_V[MM * EE], h_A[MM * EE];
__device__ __half h_X[MM * EE];
__device__ __half h_H[MM * FF];
__device__ float f_O[MM * EE], f_X1[MM * EE], f_X2[MM * EE];

// ---------------------------------------------------------------------------
// Helpers
// ---------------------------------------------------------------------------
__device__ __forceinline__ uint32_t smem_u32(const void* p) {
    uint32_t a;
    asm("{ .reg .u64 t; cvta.to.shared.u64 t, %1; cvt.u32.u64 %0, t; }"
        : "=r"(a) : "l"(p));
    return a;
}

__device__ __forceinline__ void mma_f16(float* c, const unsigned* a, const unsigned* b) {
    asm volatile(
        "mma.sync.aligned.m16n8k16.row.col.f32.f16.f16.f32 "
        "{%0,%1,%2,%3}, {%4,%5,%6,%7}, {%8,%9}, {%0,%1,%2,%3};\n"
        : "+f"(c[0]), "+f"(c[1]), "+f"(c[2]), "+f"(c[3])
        : "r"(a[0]), "r"(a[1]), "r"(a[2]), "r"(a[3]), "r"(b[0]), "r"(b[1]));
}

__device__ __forceinline__ void ldsm_x4(unsigned* r, uint32_t addr) {
    asm volatile("ldmatrix.sync.aligned.m8n8.x4.shared.b16 {%0,%1,%2,%3}, [%4];\n"
        : "=r"(r[0]), "=r"(r[1]), "=r"(r[2]), "=r"(r[3]) : "r"(addr));
}
__device__ __forceinline__ void ldsm_x4t(unsigned* r, uint32_t addr) {
    asm volatile("ldmatrix.sync.aligned.m8n8.x4.trans.shared.b16 {%0,%1,%2,%3}, [%4];\n"
        : "=r"(r[0]), "=r"(r[1]), "=r"(r[2]), "=r"(r[3]) : "r"(addr));
}

__device__ __forceinline__ void cp_async16s(uint32_t daddr, const void* src) {
    asm volatile("cp.async.cg.shared.global [%0], [%1], 16;\n" :: "r"(daddr), "l"(src));
}

__device__ __forceinline__ unsigned packh2(float x, float y) {
    __half2 h = __floats2half2_rn(x, y);
    return *reinterpret_cast<unsigned*>(&h);
}

// ---------------------------------------------------------------------------
// Fused multi-buffer fp32 -> fp16 convert (one launch for all conversions)
// ---------------------------------------------------------------------------
#define NCVT 12
struct CvtArgs {
    const float* src[NCVT];
    __half* dst[NCVT];
    int blk_start[NCVT + 1];   // block-index boundaries (each block = 1024 el)
};

__global__ __launch_bounds__(256) void f2h_multi_kernel(CvtArgs a)
{
    int bid = blockIdx.x;
    int r = 0;
    while (bid >= a.blk_start[r + 1]) r++;
    int i = ((bid - a.blk_start[r]) * 256 + threadIdx.x) * 4;
    float4 v = *reinterpret_cast<const float4*>(a.src[r] + i);
    *reinterpret_cast<__half2*>(a.dst[r] + i) = __floats2half2_rn(v.x, v.y);
    *reinterpret_cast<__half2*>(a.dst[r] + i + 2) = __floats2half2_rn(v.z, v.w);
}

// ---------------------------------------------------------------------------
// FP16 tensor-core GEMM (mma.sync m16n8k16), fp32 accumulate.
// C[M,N] = ((A[M,K] @ W[N,K]^T) + bias) * outscale, optional ReLU.
// Block tile 128x256, BK=64 halves, 256 threads = 8 warps (2x4),
// warp tile 64x64. 3-stage cp.async pipeline. Smem rows: 128B data,
// chunk-XOR swizzle (chunk ^= row&7). B fragments via ldmatrix.x4 pairs.
// ---------------------------------------------------------------------------
#define GT_A_B (128 * 128)
#define GT_B_B (256 * 128)
#define GEMM_STAGE_B (GT_A_B + GT_B_B)
#define GEMM_SMEM (3 * GEMM_STAGE_B)        // 147456 B

template <typename OutT, bool RELU>
__global__ __launch_bounds__(256, 1) void gemm_f16_kernel(
    const __half* __restrict__ A, const __half* __restrict__ W,
    const float* __restrict__ bias, OutT* __restrict__ C,
    int M, int N, int K, float outscale)
{
    extern __shared__ char gsm[];
    const uint32_t sb = smem_u32(gsm);

    const int tid = threadIdx.x;
    const int lane = tid & 31;
    const int wid = tid >> 5;
    const int wm = wid >> 2, wn = wid & 3;
    const int g = lane >> 2, t4 = lane & 3;
    const int r8 = lane & 7, hi8 = (lane >> 3) & 1, hi16 = lane >> 4;

    const int m0 = blockIdx.y * 128;
    const int n0 = blockIdx.x * 256;

    int rowOffA[4], rowOffB[4];
#pragma unroll
    for (int mt = 0; mt < 4; mt++)
        rowOffA[mt] = (wm * 64 + mt * 16 + r8 + 8 * hi8) * 128;
#pragma unroll
    for (int np = 0; np < 4; np++)   // nt pair: covers nt=2np, 2np+1
        rowOffB[np] = GT_A_B + (wn * 64 + (2 * np + hi16) * 8 + r8) * 128;

    float acc[4][8][4];
#pragma unroll
    for (int mt = 0; mt < 4; mt++)
#pragma unroll
        for (int nt = 0; nt < 8; nt++)
#pragma unroll
            for (int r = 0; r < 4; r++) acc[mt][nt][r] = 0.0f;

    const int lrow = tid >> 3;
    const int lseg = tid & 7;

    auto load_stage = [&](int st, int kb) {
        uint32_t base = sb + st * GEMM_STAGE_B;
        const __half* ag = A + (size_t)(m0 + lrow) * K + kb * 64 + lseg * 8;
#pragma unroll
        for (int it = 0; it < 4; it++) {
            int row = lrow + it * 32;
            cp_async16s(base + row * 128 + ((lseg ^ (row & 7)) << 4),
                        ag + (size_t)(it * 32) * K);
        }
        const __half* wg = W + (size_t)(n0 + lrow) * K + kb * 64 + lseg * 8;
#pragma unroll
        for (int it = 0; it < 8; it++) {
            int row = lrow + it * 32;
            cp_async16s(base + GT_A_B + row * 128 + ((lseg ^ (row & 7)) << 4),
                        wg + (size_t)(it * 32) * K);
        }
        asm volatile("cp.async.commit_group;\n" ::: "memory");
    };

    const int NK = K >> 6;

    load_stage(0, 0);
    load_stage(1, 1);
    load_stage(2, 2);

    for (int kb = 0; kb < NK; kb++) {
        if (kb < NK - 2)       asm volatile("cp.async.wait_group 2;\n" ::: "memory");
        else if (kb == NK - 2) asm volatile("cp.async.wait_group 1;\n" ::: "memory");
        else                   asm volatile("cp.async.wait_group 0;\n" ::: "memory");
        __syncthreads();

        const uint32_t sa = sb + (kb % 3) * GEMM_STAGE_B;

#pragma unroll
        for (int ks = 0; ks < 4; ks++) {
            unsigned a[4][4], bf[4][4];
            const int cA = ks * 2 + hi16;
            const int cB = ks * 2 + hi8;
#pragma unroll
            for (int mt = 0; mt < 4; mt++)
                ldsm_x4(a[mt], sa + rowOffA[mt] + ((cA ^ r8) << 4));
#pragma unroll
            for (int np = 0; np < 4; np++)
                ldsm_x4(bf[np], sa + rowOffB[np] + ((cB ^ r8) << 4));
#pragma unroll
            for (int mt = 0; mt < 4; mt++)
#pragma unroll
                for (int np = 0; np < 4; np++) {
                    mma_f16(acc[mt][2 * np], a[mt], bf[np]);
                    mma_f16(acc[mt][2 * np + 1], a[mt], bf[np] + 2);
                }
        }

        if (kb + 3 < NK) {
            __syncthreads();
            load_stage(kb % 3, kb + 3);
        }
    }

    // Epilogue
#pragma unroll
    for (int mt = 0; mt < 4; mt++) {
        int row0 = m0 + wm * 64 + mt * 16 + g;
#pragma unroll
        for (int nt = 0; nt < 8; nt++) {
            int col = n0 + wn * 64 + nt * 8 + 2 * t4;
            float b0 = bias[col], b1 = bias[col + 1];
            float v0 = (acc[mt][nt][0] + b0) * outscale;
            float v1 = (acc[mt][nt][1] + b1) * outscale;
            float v2 = (acc[mt][nt][2] + b0) * outscale;
            float v3 = (acc[mt][nt][3] + b1) * outscale;
            if (RELU) {
                v0 = fmaxf(v0, 0.0f); v1 = fmaxf(v1, 0.0f);
                v2 = fmaxf(v2, 0.0f); v3 = fmaxf(v3, 0.0f);
            }
            if (sizeof(OutT) == 2) {
                *reinterpret_cast<__half2*>((__half*)C + (size_t)row0 * N + col) =
                    __floats2half2_rn(v0, v1);
                *reinterpret_cast<__half2*>((__half*)C + (size_t)(row0 + 8) * N + col) =
                    __floats2half2_rn(v2, v3);
            } else {
                *reinterpret_cast<float2*>((float*)C + (size_t)row0 * N + col) =
                    make_float2(v0, v1);
                *reinterpret_cast<float2*>((float*)C + (size_t)(row0 + 8) * N + col) =
                    make_float2(v2, v3);
            }
        }
    }
}

// ---------------------------------------------------------------------------
// Flash attention, fp16 mma.sync, fp32 accum, base-2 softmax.
// Q PRE-SCALED by 0.125*log2(e). P is re-used directly from the S C-fragments
// as the PV A-fragments (row-major m16n8k16: C layout == A layout) -> no
// P smem round-trip. K via ldmatrix.x4 pairs, V via ldmatrix.x4.trans pairs.
// K/V double-buffered via cp.async. Causal launches reverse qb (LPT).
// Smem: Qs 16K | Ks[2] 8K | Vs[2] 8K = 48 KB.
// ---------------------------------------------------------------------------
#define FL_K0 16384
#define FL_V0 (16384 + 2 * 8192)
#define FLASH_SMEM (FL_V0 + 2 * 8192)   // 49152 B

__global__ __launch_bounds__(256, 2) void flash_f16_kernel(
    const __half* __restrict__ Q, const __half* __restrict__ K,
    const __half* __restrict__ V, __half* __restrict__ O,
    int causal)
{
    extern __shared__ char fsm[];
    const uint32_t sb = smem_u32(fsm);

    const int tid = threadIdx.x;
    const int lane = tid & 31;
    const int wid = tid >> 5;
    const int g = lane >> 2, t4 = lane & 3;
    const int r8 = lane & 7, hi8 = (lane >> 3) & 1, hi16 = lane >> 4;
    const int qr = wid * 16;

    const int qb = causal ? (gridDim.x - 1 - blockIdx.x) : blockIdx.x;
    const int h = blockIdx.y;
    const int b = blockIdx.z;

    // Load Q tile [128 x 64] fp16 (swizzled)
#pragma unroll
    for (int it = 0; it < 4; it++) {
        int f = tid + it * 256;
        int row = f >> 3, seg = f & 7;
        uint4 v = *reinterpret_cast<const uint4*>(
            &Q[((size_t)(qb * 128 + row) * BB + b) * EE + h * HD + seg * 8]);
        *reinterpret_cast<uint4*>(fsm + row * 128 + ((seg ^ (row & 7)) << 4)) = v;
    }

    const uint32_t baseQ = sb + (qr + r8 + 8 * hi8) * 128;

    auto load_kv = [&](int buf, int kt) {
#pragma unroll
        for (int it = 0; it < 4; it++) {
            int f = tid + it * 256;
            int mat = f >> 9;            // 0 = K, 1 = V
            int row = (f >> 3) & 63, seg = f & 7;
            const __half* src = (mat ? V : K) +
                ((size_t)(kt * 64 + row) * BB + b) * EE + h * HD + seg * 8;
            cp_async16s(sb + (mat ? FL_V0 : FL_K0) + buf * 8192 +
                        row * 128 + ((seg ^ (row & 7)) << 4), src);
        }
        asm volatile("cp.async.commit_group;\n" ::: "memory");
    };

    float o[8][4];
#pragma unroll
    for (int nt = 0; nt < 8; nt++)
#pragma unroll
        for (int r = 0; r < 4; r++) o[nt][r] = 0.0f;
    float m0_ = -1e30f, m1_ = -1e30f, l0_ = 0.0f, l1_ = 0.0f;

    const int nkt = causal ? (2 * qb + 2) : (SK / 64);

    load_kv(0, 0);

    for (int kt = 0; kt < nkt; kt++) {
        asm volatile("cp.async.wait_group 0;\n" ::: "memory");
        __syncthreads();   // K/V(kt) visible; prior reads of other buffer done
        if (kt + 1 < nkt) load_kv((kt + 1) & 1, kt + 1);

        const uint32_t sk = sb + FL_K0 + (kt & 1) * 8192;
        const uint32_t sv = sb + FL_V0 + (kt & 1) * 8192 + (r8 + 8 * hi8) * 128;

        // S = Q K^T  (warp m16 x n64, k=64: 4 k16 steps; K via x4 pairs)
        float s[8][4];
#pragma unroll
        for (int nt = 0; nt < 8; nt++)
#pragma unroll
            for (int r = 0; r < 4; r++) s[nt][r] = 0.0f;

#pragma unroll
        for (int ks = 0; ks < 4; ks++) {
            unsigned a[4];
            ldsm_x4(a, baseQ + (((ks * 2 + hi16) ^ r8) << 4));
            const int cB = ks * 2 + hi8;
#pragma unroll
            for (int np = 0; np < 4; np++) {
                unsigned bf[4];
                ldsm_x4(bf, sk + ((2 * np + hi16) * 8 + r8) * 128 + ((cB ^ r8) << 4));
                mma_f16(s[2 * np], a, bf);
                mma_f16(s[2 * np + 1], a, bf + 2);
            }
        }

        // Causal mask (diagonal-overlapping tiles only)
        if (causal && kt >= 2 * qb) {
            int row0 = qb * 128 + qr + g;
            int row1 = row0 + 8;
#pragma unroll
            for (int nt = 0; nt < 8; nt++) {
                int col = kt * 64 + nt * 8 + 2 * t4;
                if (col > row0)     s[nt][0] = -1e30f;
                if (col + 1 > row0) s[nt][1] = -1e30f;
                if (col > row1)     s[nt][2] = -1e30f;
                if (col + 1 > row1) s[nt][3] = -1e30f;
            }
        }

        // Online softmax, base 2 (thread owns rows g, g+8)
        float mx0 = -1e30f, mx1 = -1e30f;
#pragma unroll
        for (int nt = 0; nt < 8; nt++) {
            mx0 = fmaxf(mx0, fmaxf(s[nt][0], s[nt][1]));
            mx1 = fmaxf(mx1, fmaxf(s[nt][2], s[nt][3]));
        }
        mx0 = fmaxf(mx0, __shfl_xor_sync(0xffffffffu, mx0, 1));
        mx0 = fmaxf(mx0, __shfl_xor_sync(0xffffffffu, mx0, 2));
        mx1 = fmaxf(mx1, __shfl_xor_sync(0xffffffffu, mx1, 1));
        mx1 = fmaxf(mx1, __shfl_xor_sync(0xffffffffu, mx1, 2));

        float nm0 = fmaxf(m0_, mx0);
        float nm1 = fmaxf(m1_, mx1);
        float corr0 = exp2f(m0_ - nm0);
        float corr1 = exp2f(m1_ - nm1);
        m0_ = nm0; m1_ = nm1;

        float sum0 = 0.0f, sum1 = 0.0f;
        unsigned p2[8][2];
#pragma unroll
        for (int nt = 0; nt < 8; nt++) {
            float e0 = exp2f(s[nt][0] - nm0);
            float e1 = exp2f(s[nt][1] - nm0);
            float e2 = exp2f(s[nt][2] - nm1);
            float e3 = exp2f(s[nt][3] - nm1);
            sum0 += e0 + e1;
            sum1 += e2 + e3;
            p2[nt][0] = packh2(e0, e1);
            p2[nt][1] = packh2(e2, e3);
        }
        sum0 += __shfl_xor_sync(0xffffffffu, sum0, 1);
        sum0 += __shfl_xor_sync(0xffffffffu, sum0, 2);
        sum1 += __shfl_xor_sync(0xffffffffu, sum1, 1);
        sum1 += __shfl_xor_sync(0xffffffffu, sum1, 2);
        l0_ = l0_ * corr0 + sum0;
        l1_ = l1_ * corr1 + sum1;
#pragma unroll
        for (int nt = 0; nt < 8; nt++) {
            o[nt][0] *= corr0; o[nt][1] *= corr0;
            o[nt][2] *= corr1; o[nt][3] *= corr1;
        }

        // O += P @ V  (A = p2 registers directly; B via ldmatrix.x4.trans pairs)
#pragma unroll
        for (int ks = 0; ks < 4; ks++) {
            unsigned a[4] = {p2[2 * ks][0], p2[2 * ks][1],
                             p2[2 * ks + 1][0], p2[2 * ks + 1][1]};
            const uint32_t bv = sv + ks * 16 * 128;
#pragma unroll
            for (int np = 0; np < 4; np++) {
                unsigned bf[4];
                ldsm_x4t(bf, bv + (((2 * np + hi16) ^ r8) << 4));
                mma_f16(o[2 * np], a, bf);
                mma_f16(o[2 * np + 1], a, bf + 2);
            }
        }
    }

    // Normalize + store fp16
    float inv0 = 1.0f / l0_;
    float inv1 = 1.0f / l1_;
    int tok0 = qb * 128 + qr + g;
#pragma unroll
    for (int nt = 0; nt < 8; nt++) {
        int col = h * HD + nt * 8 + 2 * t4;
        *reinterpret_cast<__half2*>(&O[((size_t)tok0 * BB + b) * EE + col]) =
            __floats2half2_rn(o[nt][0] * inv0, o[nt][1] * inv0);
        *reinterpret_cast<__half2*>(&O[((size_t)(tok0 + 8) * BB + b) * EE + col]) =
            __floats2half2_rn(o[nt][2] * inv1, o[nt][3] * inv1);
    }
}

// ---------------------------------------------------------------------------
// Fused add + LayerNorm: out = LN(x + y) * g + b (row length 1024).
// Optionally also writes an fp16 copy (out16 != nullptr).
// ---------------------------------------------------------------------------
__global__ __launch_bounds__(256) void add_ln_kernel(
    const float* __restrict__ X, const float* __restrict__ Y,
    const float* __restrict__ gamma, const float* __restrict__ beta,
    float* __restrict__ out, __half* __restrict__ out16)
{
    const int row = blockIdx.x;
    const int tid = threadIdx.x;
    const size_t base = (size_t)row * EE + tid * 4;

    float4 xv = *reinterpret_cast<const float4*>(&X[base]);
    float4 yv = *reinterpret_cast<const float4*>(&Y[base]);
    float v0 = xv.x + yv.x, v1 = xv.y + yv.y, v2 = xv.z + yv.z, v3 = xv.w + yv.w;

    float s1 = v0 + v1 + v2 + v3;
    float s2 = v0 * v0 + v1 * v1 + v2 * v2 + v3 * v3;

    __shared__ float sm1[8], sm2[8];
#pragma unroll
    for (int off = 16; off > 0; off >>= 1) {
        s1 += __shfl_xor_sync(0xffffffffu, s1, off);
        s2 += __shfl_xor_sync(0xffffffffu, s2, off);
    }
    int wid = tid >> 5, lid = tid & 31;
    if (lid == 0) { sm1[wid] = s1; sm2[wid] = s2; }
    __syncthreads();
    if (wid == 0) {
        s1 = (lid < 8) ? sm1[lid] : 0.0f;
        s2 = (lid < 8) ? sm2[lid] : 0.0f;
#pragma unroll
        for (int off = 4; off > 0; off >>= 1) {
            s1 += __shfl_xor_sync(0xffffffffu, s1, off);
            s2 += __shfl_xor_sync(0xffffffffu, s2, off);
        }
        if (lid == 0) { sm1[0] = s1; sm2[0] = s2; }
    }
    __syncthreads();
    float mean = sm1[0] * (1.0f / EE);
    float var = sm2[0] * (1.0f / EE) - mean * mean;
    float r = rsqrtf(var + 1e-5f);

    int c = tid * 4;
    float4 gv = *reinterpret_cast<const float4*>(&gamma[c]);
    float4 bv = *reinterpret_cast<const float4*>(&beta[c]);
    float4 ov;
    ov.x = (v0 - mean) * r * gv.x + bv.x;
    ov.y = (v1 - mean) * r * gv.y + bv.y;
    ov.z = (v2 - mean) * r * gv.z + bv.z;
    ov.w = (v3 - mean) * r * gv.w + bv.w;
    *reinterpret_cast<float4*>(&out[base]) = ov;
    if (out16) {
        *reinterpret_cast<__half2*>(out16 + base) = __floats2half2_rn(ov.x, ov.y);
        *reinterpret_cast<__half2*>(out16 + base + 2) = __floats2half2_rn(ov.z, ov.w);
    }
}

// ---------------------------------------------------------------------------
// Host orchestration
// ---------------------------------------------------------------------------
#define QSCALE (0.125f * 1.4426950408889634f)   // 1/sqrt(HD) * log2(e)

template <typename OutT, bool RELU>
static void launch_gemm(const __half* A, const __half* W, const float* bias,
                        OutT* C, int M, int N, int K, float outscale = 1.0f)
{
    dim3 grid(N / 256, M / 128);
    gemm_f16_kernel<OutT, RELU><<<grid, 256, GEMM_SMEM>>>(A, W, bias, C, M, N, K, outscale);
}

extern "C" void kernel_launch(void* const* d_in, const int* in_sizes, int n_in,
                              void* d_out, int out_size)
{
    const float* tgt    = (const float*)d_in[0];
    const float* memory = (const float*)d_in[1];
    // d_in[2] = tgt_mask (causal; implemented directly)
    const float* sa_Wq = (const float*)d_in[3];
    const float* sa_bq = (const float*)d_in[4];
    const float* sa_Wk = (const float*)d_in[5];
    const float* sa_bk = (const float*)d_in[6];
    const float* sa_Wv = (const float*)d_in[7];
    const float* sa_bv = (const float*)d_in[8];
    const float* sa_Wo = (const float*)d_in[9];
    const float* sa_bo = (const float*)d_in[10];
    const float* ca_Wq = (const float*)d_in[11];
    const float* ca_bq = (const float*)d_in[12];
    const float* ca_Wk = (const float*)d_in[13];
    const float* ca_bk = (const float*)d_in[14];
    const float* ca_Wv = (const float*)d_in[15];
    const float* ca_bv = (const float*)d_in[16];
    const float* ca_Wo = (const float*)d_in[17];
    const float* ca_bo = (const float*)d_in[18];
    const float* W1    = (const float*)d_in[19];
    const float* b1    = (const float*)d_in[20];
    const float* W2    = (const float*)d_in[21];
    const float* b2    = (const float*)d_in[22];
    const float* ln1_g = (const float*)d_in[23];
    const float* ln1_b = (const float*)d_in[24];
    const float* ln2_g = (const float*)d_in[25];
    const float* ln2_b = (const float*)d_in[26];
    const float* ln3_g = (const float*)d_in[27];
    const float* ln3_b = (const float*)d_in[28];
    float* out = (float*)d_out;

    __half *pWsaq, *pWsak, *pWsav, *pWsao, *pWcaq, *pWcak, *pWcav, *pWcao;
    __half *pW1, *pW2, *pTgt, *pMem, *pQ, *pK, *pV, *pA, *pX, *pH;
    float *pO, *pX1, *pX2;
    cudaGetSymbolAddress((void**)&pWsaq, hW_saq);
    cudaGetSymbolAddress((void**)&pWsak, hW_sak);
    cudaGetSymbolAddress((void**)&pWsav, hW_sav);
    cudaGetSymbolAddress((void**)&pWsao, hW_sao);
    cudaGetSymbolAddress((void**)&pWcaq, hW_caq);
    cudaGetSymbolAddress((void**)&pWcak, hW_cak);
    cudaGetSymbolAddress((void**)&pWcav, hW_cav);
    cudaGetSymbolAddress((void**)&pWcao, hW_cao);
    cudaGetSymbolAddress((void**)&pW1, hW1);
    cudaGetSymbolAddress((void**)&pW2, hW2);
    cudaGetSymbolAddress((void**)&pTgt, h_tgt);
    cudaGetSymbolAddress((void**)&pMem, h_mem);
    cudaGetSymbolAddress((void**)&pQ, h_Q);
    cudaGetSymbolAddress((void**)&pK, h_K);
    cudaGetSymbolAddress((void**)&pV, h_V);
    cudaGetSymbolAddress((void**)&pA, h_A);
    cudaGetSymbolAddress((void**)&pX, h_X);
    cudaGetSymbolAddress((void**)&pH, h_H);
    cudaGetSymbolAddress((void**)&pO, f_O);
    cudaGetSymbolAddress((void**)&pX1, f_X1);
    cudaGetSymbolAddress((void**)&pX2, f_X2);

    cudaFuncSetAttribute(gemm_f16_kernel<float, false>,
                         cudaFuncAttributeMaxDynamicSharedMemorySize, GEMM_SMEM);
    cudaFuncSetAttribute(gemm_f16_kernel<__half, false>,
                         cudaFuncAttributeMaxDynamicSharedMemorySize, GEMM_SMEM);
    cudaFuncSetAttribute(gemm_f16_kernel<__half, true>,
                         cudaFuncAttributeMaxDynamicSharedMemorySize, GEMM_SMEM);
    cudaFuncSetAttribute(flash_f16_kernel,
                         cudaFuncAttributeMaxDynamicSharedMemorySize, FLASH_SMEM);

    // ---- One fused conversion launch for all weights + inputs ----
    {
        CvtArgs ca;
        const float* srcs[NCVT] = {sa_Wq, sa_Wk, sa_Wv, sa_Wo, ca_Wq, ca_Wk,
                                   ca_Wv, ca_Wo, W1, W2, tgt, memory};
        __half* dsts[NCVT] = {pWsaq, pWsak, pWsav, pWsao, pWcaq, pWcak,
                              pWcav, pWcao, pW1, pW2, pTgt, pMem};
        int sizes[NCVT] = {EE * EE, EE * EE, EE * EE, EE * EE, EE * EE, EE * EE,
                           EE * EE, EE * EE, FF * EE, EE * FF, MM * EE, MM * EE};
        int acc = 0;
        for (int i = 0; i < NCVT; i++) {
            ca.src[i] = srcs[i];
            ca.dst[i] = dsts[i];
            ca.blk_start[i] = acc;
            acc += sizes[i] / 1024;
        }
        ca.blk_start[NCVT] = acc;
        f2h_multi_kernel<<<acc, 256>>>(ca);
    }

    dim3 attn_grid(LQ / 128, HH, BB);

    // ---- Self-attention block ----
    launch_gemm<__half, false>(pTgt, pWsaq, sa_bq, pQ, MM, EE, EE, QSCALE);
    launch_gemm<__half, false>(pTgt, pWsak, sa_bk, pK, MM, EE, EE);
    launch_gemm<__half, false>(pTgt, pWsav, sa_bv, pV, MM, EE, EE);
    flash_f16_kernel<<<attn_grid, 256, FLASH_SMEM>>>(pQ, pK, pV, pA, 1);
    launch_gemm<float, false>(pA, pWsao, sa_bo, pO, MM, EE, EE);
    add_ln_kernel<<<MM, 256>>>(tgt, pO, ln1_g, ln1_b, pX1, pX);

    // ---- Cross-attention block ----
    launch_gemm<__half, false>(pX, pWcaq, ca_bq, pQ, MM, EE, EE, QSCALE);
    launch_gemm<__half, false>(pMem, pWcak, ca_bk, pK, MM, EE, EE);
    launch_gemm<__half, false>(pMem, pWcav, ca_bv, pV, MM, EE, EE);
    flash_f16_kernel<<<attn_grid, 256, FLASH_SMEM>>>(pQ, pK, pV, pA, 0);
    launch_gemm<float, false>(pA, pWcao, ca_bo, pO, MM, EE, EE);
    add_ln_kernel<<<MM, 256>>>(pX1, pO, ln2_g, ln2_b, pX2, pX);

    // ---- FFN block ----
    launch_gemm<__half, true>(pX, pW1, b1, pH, MM, FF, EE);
    launch_gemm<float, false>(pH, pW2, b2, pO, MM, EE, FF);
    add_ln_kernel<<<MM, 256>>>(pX2, pO, ln3_g, ln3_b, out, nullptr);
}